// round 12
// baseline (speedup 1.0000x reference)
#include <cuda_runtime.h>
#include <cuda_bf16.h>
#include <cuda_fp16.h>
#include <cstdint>

#define NN 100000
#define NE 1600000
#define NP 500000
#define DD 128
#define SCAN_B 512
#define NBLK ((NN + SCAN_B - 1) / SCAN_B)   // 196

#define WSTRIDE 136                  // bf16 elems per padded row (272 B)
#define WIMG_HALF (128 * WSTRIDE)    // 17408 elems per hi/lo image
#define WIMG_LAYER (2 * WIMG_HALF)   // 34816 elems (hi+lo) per layer
#define TILE_M 64
#define GEMM_GRID 296                // 2 CTAs/SM x 148 SMs (persistent)

// Scratch (device globals: allocation-free rule)
__device__ float g_bufA[(size_t)NN * DD];   // H1'/H2' fp16 images (low half used)
__device__ float g_bufB[(size_t)NN * DD];   // G16 fp16 image
__device__ int   g_deg[NN];
__device__ float g_dinv[NN];
__device__ int   g_rowptr[NN + 1];
__device__ int   g_cursor[NN];
__device__ int   g_col[NE];
__device__ int   g_bsum[NBLK];
__device__ int   g_boff[NBLK];
__device__ __align__(16) __nv_bfloat16 g_Wimg[2 * WIMG_LAYER];  // 139 KB

// ===========================================================================
// mma.sync / ldmatrix helpers (base ISA, works on compute_103 target)
// ===========================================================================
__device__ __forceinline__ uint32_t smem_u32(const void* p) {
    uint32_t a;
    asm("{ .reg .u64 t; cvta.to.shared.u64 t, %1; cvt.u32.u64 %0, t; }"
        : "=r"(a) : "l"(p));
    return a;
}
__device__ __forceinline__ void ldm_x4(uint32_t& r0, uint32_t& r1,
                                       uint32_t& r2, uint32_t& r3, uint32_t addr) {
    asm volatile("ldmatrix.sync.aligned.m8n8.x4.shared.b16 {%0,%1,%2,%3}, [%4];"
                 : "=r"(r0), "=r"(r1), "=r"(r2), "=r"(r3) : "r"(addr));
}
__device__ __forceinline__ void ldm_x2t(uint32_t& r0, uint32_t& r1, uint32_t addr) {
    asm volatile("ldmatrix.sync.aligned.m8n8.x2.trans.shared.b16 {%0,%1}, [%2];"
                 : "=r"(r0), "=r"(r1) : "r"(addr));
}
__device__ __forceinline__ void mma_bf16(float* c, uint32_t a0, uint32_t a1,
                                         uint32_t a2, uint32_t a3,
                                         uint32_t b0, uint32_t b1) {
    asm volatile(
        "mma.sync.aligned.m16n8k16.row.col.f32.bf16.bf16.f32 "
        "{%0,%1,%2,%3}, {%4,%5,%6,%7}, {%8,%9}, {%0,%1,%2,%3};"
        : "+f"(c[0]), "+f"(c[1]), "+f"(c[2]), "+f"(c[3])
        : "r"(a0), "r"(a1), "r"(a2), "r"(a3), "r"(b0), "r"(b1));
}
__device__ __forceinline__ float4 h4_to_f4(uint2 u) {
    __half2 h0 = *(__half2*)&u.x;
    __half2 h1 = *(__half2*)&u.y;
    float2 f0 = __half22float2(h0);
    float2 f1 = __half22float2(h1);
    return make_float4(f0.x, f0.y, f1.x, f1.y);
}
// split 4 fp32 -> bf16 hi (uint2) and lo (uint2)
__device__ __forceinline__ void split4(float4 v, uint2& hi, uint2& lo) {
    __nv_bfloat16 hx = __float2bfloat16(v.x), hy = __float2bfloat16(v.y);
    __nv_bfloat16 hz = __float2bfloat16(v.z), hw = __float2bfloat16(v.w);
    __nv_bfloat16 lx = __float2bfloat16(v.x - __bfloat162float(hx));
    __nv_bfloat16 ly = __float2bfloat16(v.y - __bfloat162float(hy));
    __nv_bfloat16 lz = __float2bfloat16(v.z - __bfloat162float(hz));
    __nv_bfloat16 lw = __float2bfloat16(v.w - __bfloat162float(hw));
    __nv_bfloat162 a; a.x = hx; a.y = hy; hi.x = *(uint32_t*)&a;
    __nv_bfloat162 b; b.x = hz; b.y = hw; hi.y = *(uint32_t*)&b;
    __nv_bfloat162 c; c.x = lx; c.y = ly; lo.x = *(uint32_t*)&c;
    __nv_bfloat162 d; d.x = lz; d.y = lw; lo.y = *(uint32_t*)&d;
}

// ---------------------------------------------------------------------------
// Degree
// ---------------------------------------------------------------------------
__global__ void init_deg_k(int* __restrict__ deg) {
    int i = blockIdx.x * blockDim.x + threadIdx.x;
    if (i < NN) deg[i] = 1;  // self loop
}

__global__ void count_deg_k(const int* __restrict__ dst, int* __restrict__ deg) {
    int i = blockIdx.x * blockDim.x + threadIdx.x;
    int stride = gridDim.x * blockDim.x;
    for (int e = i; e < NE; e += stride)
        atomicAdd(&deg[dst[e]], 1);
}

// ---------------------------------------------------------------------------
// W split: W[k][n] fp32 -> k-major bf16 images [128][WSTRIDE] hi then lo.
// ---------------------------------------------------------------------------
__global__ void wsplit_k(const float* __restrict__ W1, const float* __restrict__ W2,
                         __nv_bfloat16* __restrict__ img) {
    int i = blockIdx.x * blockDim.x + threadIdx.x;
    if (i >= 2 * WIMG_HALF) return;
    int L = i / WIMG_HALF;
    int rem = i % WIMG_HALF;
    int k = rem / WSTRIDE;
    int n = rem % WSTRIDE;
    const float* W = L ? W2 : W1;
    float v = (n < 128) ? W[k * 128 + n] : 0.f;
    __nv_bfloat16 h = __float2bfloat16(v);
    __nv_bfloat16 l = __float2bfloat16(v - __bfloat162float(h));
    img[(size_t)L * WIMG_LAYER + rem] = h;
    img[(size_t)L * WIMG_LAYER + WIMG_HALF + rem] = l;
}

// ---------------------------------------------------------------------------
// CSR build (scan1 also emits dinv = rsqrt(deg))
// ---------------------------------------------------------------------------
__global__ void scan1_k(const int* __restrict__ deg, int* __restrict__ bsum,
                        float* __restrict__ dinv) {
    __shared__ int s[SCAN_B];
    int t = threadIdx.x;
    int i = blockIdx.x * SCAN_B + t;
    int d = (i < NN) ? deg[i] : 1;
    if (i < NN) dinv[i] = rsqrtf((float)d);
    s[t] = (i < NN) ? (d - 1) : 0;
    __syncthreads();
    for (int off = SCAN_B / 2; off > 0; off >>= 1) {
        if (t < off) s[t] += s[t + off];
        __syncthreads();
    }
    if (t == 0) bsum[blockIdx.x] = s[0];
}

__global__ void scan2_k(const int* __restrict__ bsum, int* __restrict__ boff) {
    __shared__ int s[NBLK];
    int t = threadIdx.x;
    for (int i = t; i < NBLK; i += blockDim.x) s[i] = bsum[i];
    __syncthreads();
    if (t == 0) {
        int run = 0;
        for (int b = 0; b < NBLK; b++) { int v = s[b]; s[b] = run; run += v; }
    }
    __syncthreads();
    for (int i = t; i < NBLK; i += blockDim.x) boff[i] = s[i];
}

__global__ void scan3_k(const int* __restrict__ deg, const int* __restrict__ boff,
                        int* __restrict__ rowptr, int* __restrict__ cursor) {
    __shared__ int s[2][SCAN_B];
    int t = threadIdx.x;
    int i = blockIdx.x * SCAN_B + t;
    int v = (i < NN) ? (deg[i] - 1) : 0;
    s[0][t] = v;
    __syncthreads();
    int pp = 0;
    for (int off = 1; off < SCAN_B; off <<= 1) {
        int nv = s[pp][t] + ((t >= off) ? s[pp][t - off] : 0);
        s[1 - pp][t] = nv;
        pp = 1 - pp;
        __syncthreads();
    }
    if (i < NN) {
        int excl = s[pp][t] - v + boff[blockIdx.x];
        rowptr[i] = excl;
        cursor[i] = excl;
        if (i == NN - 1) rowptr[NN] = excl + v;
    }
}

__global__ void fill_k(const int* __restrict__ src, const int* __restrict__ dst,
                       int* __restrict__ cursor, int* __restrict__ col) {
    int i = blockIdx.x * blockDim.x + threadIdx.x;
    int stride = gridDim.x * blockDim.x;
    for (int e = i; e < NE; e += stride) {
        int d = dst[e];
        int pos = atomicAdd(&cursor[d], 1);
        col[pos] = src[e];
    }
}

// ---------------------------------------------------------------------------
// MMA core: acc[8][4] += A(16 rows, hi+lo split) x W(hi+lo), then fp16 store.
// Shared by both gemm kernels. Warps: mw = wid&3 (m-tile), nh = wid>>2.
// ---------------------------------------------------------------------------
__device__ __forceinline__ void mma_and_store(uint32_t aHiBase, uint32_t aLoBase,
                                              uint32_t bBase, int r0, int mw,
                                              int nh, int lane,
                                              __half* __restrict__ Hs,
                                              const float* __restrict__ dinv,
                                              int nrows) {
    float acc[8][4];
#pragma unroll
    for (int nt = 0; nt < 8; nt++)
#pragma unroll
        for (int q = 0; q < 4; q++) acc[nt][q] = 0.f;

#pragma unroll 1
    for (int ks = 0; ks < 8; ks++) {
        uint32_t a0, a1, a2, a3;
        ldm_x4(a0, a1, a2, a3, aHiBase + ks * 32);
        uint32_t bk = bBase + ks * 16 * (WSTRIDE * 2);
#pragma unroll
        for (int nt = 0; nt < 8; nt++) {
            uint32_t b0, b1, c0, c1;
            ldm_x2t(b0, b1, bk + nt * 16);
            mma_bf16(acc[nt], a0, a1, a2, a3, b0, b1);
            ldm_x2t(c0, c1, bk + nt * 16 + WIMG_HALF * 2);
            mma_bf16(acc[nt], a0, a1, a2, a3, c0, c1);
        }
    }
#pragma unroll 1
    for (int ks = 0; ks < 8; ks++) {
        uint32_t a0, a1, a2, a3;
        ldm_x4(a0, a1, a2, a3, aLoBase + ks * 32);
        uint32_t bk = bBase + ks * 16 * (WSTRIDE * 2);
#pragma unroll
        for (int nt = 0; nt < 8; nt++) {
            uint32_t b0, b1;
            ldm_x2t(b0, b1, bk + nt * 16);
            mma_bf16(acc[nt], a0, a1, a2, a3, b0, b1);
        }
    }

    int row0 = r0 + mw * 16 + (lane >> 2);
    int colb = nh * 64 + (lane & 3) * 2;
#pragma unroll
    for (int half = 0; half < 2; half++) {
        int row = row0 + half * 8;
        if (row < nrows) {
            float dv = dinv[row];
            __half* po = Hs + (size_t)row * 128 + colb;
#pragma unroll
            for (int nt = 0; nt < 8; nt++)
                *(__half2*)(po + nt * 8) =
                    __floats2half2_rn(acc[nt][2 * half] * dv,
                                      acc[nt][2 * half + 1] * dv);
        }
    }
}

// ---------------------------------------------------------------------------
// GEMM layer 1 (persistent): H1' = fp16(dinv * (x @ W1)). Convert from fp32 X.
// ---------------------------------------------------------------------------
__global__ void __launch_bounds__(256) gemm1_k(const float* __restrict__ X,
                                               const __nv_bfloat16* __restrict__ Wimg,
                                               __half* __restrict__ Hs,
                                               const float* __restrict__ dinv,
                                               int nrows, int ntiles) {
    extern __shared__ __align__(16) unsigned char sm[];
    __nv_bfloat16* sW   = (__nv_bfloat16*)(sm + 512);
    __nv_bfloat16* sAhi = (__nv_bfloat16*)(sm + 512 + 2 * WIMG_HALF * 2);
    __nv_bfloat16* sAlo = sAhi + TILE_M * WSTRIDE;
    int tid = threadIdx.x, wid = tid >> 5, lane = tid & 31;
    int mw = wid & 3, nh = wid >> 2;

    for (int i = tid; i < (2 * WIMG_HALF * 2) / 16; i += 256)
        ((uint4*)sW)[i] = ((const uint4*)Wimg)[i];
    __syncthreads();

    uint32_t aHiBase = smem_u32(sAhi) + (mw * 16 + (lane & 15)) * (WSTRIDE * 2)
                     + (lane >> 4) * 16;
    uint32_t aLoBase = aHiBase + TILE_M * WSTRIDE * 2;
    uint32_t bBase = smem_u32(sW) + (lane & 15) * (WSTRIDE * 2) + nh * 128;

    for (int t = blockIdx.x; t < ntiles; t += gridDim.x) {
        int r0 = t * TILE_M;
        // convert: thread = (row tid/4, 32-col quarter tid%4)
        {
            int m = tid >> 2;
            int c0 = (tid & 3) << 5;
            long r = (long)r0 + m;
            bool valid = r < nrows;
            const float4* Xv = (const float4*)(X + (size_t)r * 128 + c0);
            uint2* dh = (uint2*)(sAhi + m * WSTRIDE + c0);
            uint2* dl = (uint2*)(sAlo + m * WSTRIDE + c0);
#pragma unroll
            for (int j = 0; j < 8; j++) {
                float4 v = valid ? Xv[j] : make_float4(0.f, 0.f, 0.f, 0.f);
                uint2 hi, lo;
                split4(v, hi, lo);
                dh[j] = hi;
                dl[j] = lo;
            }
        }
        __syncthreads();
        mma_and_store(aHiBase, aLoBase, bBase, r0, mw, nh, lane, Hs, dinv, nrows);
        __syncthreads();
    }
}

// ---------------------------------------------------------------------------
// FUSED gather + GEMM layer 2 (persistent):
//   per tile row r: agg = dinv[r] * (H1'[r] + sum_in H1'[s]);  a = relu(agg+b1)
//   -> bf16 split to smem -> MMA -> H2' = fp16(dinv * (a @ W2))
// AGG1 never touches global memory. Warp w gathers rows w*8..w*8+7.
// ---------------------------------------------------------------------------
__global__ void __launch_bounds__(256) gemm2_fused_k(const __half* __restrict__ H1,
                                                     const __nv_bfloat16* __restrict__ Wimg,
                                                     const float* __restrict__ b1,
                                                     const int* __restrict__ rowptr,
                                                     const int* __restrict__ col,
                                                     __half* __restrict__ Hs,
                                                     const float* __restrict__ dinv,
                                                     int nrows, int ntiles) {
    extern __shared__ __align__(16) unsigned char sm[];
    float* sbias = (float*)sm;                                    // 512 B
    __nv_bfloat16* sW   = (__nv_bfloat16*)(sm + 512);
    __nv_bfloat16* sAhi = (__nv_bfloat16*)(sm + 512 + 2 * WIMG_HALF * 2);
    __nv_bfloat16* sAlo = sAhi + TILE_M * WSTRIDE;
    int tid = threadIdx.x, wid = tid >> 5, lane = tid & 31;
    int mw = wid & 3, nh = wid >> 2;

    if (tid < 32) ((float4*)sbias)[tid] = ((const float4*)b1)[tid];
    for (int i = tid; i < (2 * WIMG_HALF * 2) / 16; i += 256)
        ((uint4*)sW)[i] = ((const uint4*)Wimg)[i];
    __syncthreads();

    uint32_t aHiBase = smem_u32(sAhi) + (mw * 16 + (lane & 15)) * (WSTRIDE * 2)
                     + (lane >> 4) * 16;
    uint32_t aLoBase = aHiBase + TILE_M * WSTRIDE * 2;
    uint32_t bBase = smem_u32(sW) + (lane & 15) * (WSTRIDE * 2) + nh * 128;

    float4 bv = ((const float4*)sbias)[lane];

    for (int t = blockIdx.x; t < ntiles; t += gridDim.x) {
        int r0 = t * TILE_M;
        // Phase G: warp wid gathers+converts rows wid*8 .. wid*8+7
#pragma unroll 1
        for (int i = 0; i < 8; i++) {
            int m = wid * 8 + i;
            long r = (long)r0 + m;
            float4 a0 = make_float4(0.f, 0.f, 0.f, 0.f);
            if (r < nrows) {
                a0 = h4_to_f4(((const uint2*)(H1 + (size_t)r * 128))[lane]);
                float4 a1 = make_float4(0.f, 0.f, 0.f, 0.f), a2 = a1, a3 = a1;
                int j = rowptr[r];
                int end = rowptr[r + 1];
                for (; j + 3 < end; j += 4) {
                    int s0 = __ldg(&col[j]);
                    int s1 = __ldg(&col[j + 1]);
                    int s2 = __ldg(&col[j + 2]);
                    int s3 = __ldg(&col[j + 3]);
                    float4 v0 = h4_to_f4(((const uint2*)(H1 + (size_t)s0 * 128))[lane]);
                    float4 v1 = h4_to_f4(((const uint2*)(H1 + (size_t)s1 * 128))[lane]);
                    float4 v2 = h4_to_f4(((const uint2*)(H1 + (size_t)s2 * 128))[lane]);
                    float4 v3 = h4_to_f4(((const uint2*)(H1 + (size_t)s3 * 128))[lane]);
                    a0.x += v0.x; a0.y += v0.y; a0.z += v0.z; a0.w += v0.w;
                    a1.x += v1.x; a1.y += v1.y; a1.z += v1.z; a1.w += v1.w;
                    a2.x += v2.x; a2.y += v2.y; a2.z += v2.z; a2.w += v2.w;
                    a3.x += v3.x; a3.y += v3.y; a3.z += v3.z; a3.w += v3.w;
                }
                for (; j < end; j++) {
                    int s0 = __ldg(&col[j]);
                    float4 v0 = h4_to_f4(((const uint2*)(H1 + (size_t)s0 * 128))[lane]);
                    a0.x += v0.x; a0.y += v0.y; a0.z += v0.z; a0.w += v0.w;
                }
                float dn = dinv[r];
                a0.x = fmaxf(fmaf(a0.x + a1.x + a2.x + a3.x, dn, bv.x), 0.f);
                a0.y = fmaxf(fmaf(a0.y + a1.y + a2.y + a3.y, dn, bv.y), 0.f);
                a0.z = fmaxf(fmaf(a0.z + a1.z + a2.z + a3.z, dn, bv.z), 0.f);
                a0.w = fmaxf(fmaf(a0.w + a1.w + a2.w + a3.w, dn, bv.w), 0.f);
            }
            uint2 hi, lo;
            split4(a0, hi, lo);
            *(uint2*)(sAhi + m * WSTRIDE + lane * 4) = hi;
            *(uint2*)(sAlo + m * WSTRIDE + lane * 4) = lo;
        }
        __syncthreads();
        mma_and_store(aHiBase, aLoBase, bBase, r0, mw, nh, lane, Hs, dinv, nrows);
        __syncthreads();
    }
}

// ---------------------------------------------------------------------------
// CSR gather (layer 2 output): G16 = fp16( dinv[n]*(H2'[n]+sum) + b2 )
// ---------------------------------------------------------------------------
__global__ void gather2_k(const __half* __restrict__ Hs,
                          const int* __restrict__ rowptr,
                          const int* __restrict__ col,
                          const float* __restrict__ dinv,
                          const float* __restrict__ b2,
                          __half* __restrict__ G) {
    int gtid = blockIdx.x * blockDim.x + threadIdx.x;
    int lane = gtid & 31;
    int w = gtid >> 5;
    int nw = (gridDim.x * blockDim.x) >> 5;
    float4 bv = ((const float4*)b2)[lane];
    for (int n = w; n < NN; n += nw) {
        float4 a0 = h4_to_f4(((const uint2*)(Hs + (size_t)n * 128))[lane]);
        float4 a1 = make_float4(0.f, 0.f, 0.f, 0.f), a2 = a1, a3 = a1;
        int j = rowptr[n];
        int end = rowptr[n + 1];
        for (; j + 3 < end; j += 4) {
            int s0 = __ldg(&col[j]);
            int s1 = __ldg(&col[j + 1]);
            int s2 = __ldg(&col[j + 2]);
            int s3 = __ldg(&col[j + 3]);
            float4 v0 = h4_to_f4(((const uint2*)(Hs + (size_t)s0 * 128))[lane]);
            float4 v1 = h4_to_f4(((const uint2*)(Hs + (size_t)s1 * 128))[lane]);
            float4 v2 = h4_to_f4(((const uint2*)(Hs + (size_t)s2 * 128))[lane]);
            float4 v3 = h4_to_f4(((const uint2*)(Hs + (size_t)s3 * 128))[lane]);
            a0.x += v0.x; a0.y += v0.y; a0.z += v0.z; a0.w += v0.w;
            a1.x += v1.x; a1.y += v1.y; a1.z += v1.z; a1.w += v1.w;
            a2.x += v2.x; a2.y += v2.y; a2.z += v2.z; a2.w += v2.w;
            a3.x += v3.x; a3.y += v3.y; a3.z += v3.z; a3.w += v3.w;
        }
        for (; j < end; j++) {
            int s0 = __ldg(&col[j]);
            float4 v0 = h4_to_f4(((const uint2*)(Hs + (size_t)s0 * 128))[lane]);
            a0.x += v0.x; a0.y += v0.y; a0.z += v0.z; a0.w += v0.w;
        }
        float dn = dinv[n];
        a0.x = fmaf(a0.x + a1.x + a2.x + a3.x, dn, bv.x);
        a0.y = fmaf(a0.y + a1.y + a2.y + a3.y, dn, bv.y);
        a0.z = fmaf(a0.z + a1.z + a2.z + a3.z, dn, bv.z);
        a0.w = fmaf(a0.w + a1.w + a2.w + a3.w, dn, bv.w);
        uint2 u;
        *(__half2*)&u.x = __floats2half2_rn(a0.x, a0.y);
        *(__half2*)&u.y = __floats2half2_rn(a0.z, a0.w);
        ((uint2*)(G + (size_t)n * 128))[lane] = u;
    }
}

// ---------------------------------------------------------------------------
// Pair dot products on fp16 G (bias pre-added)
// ---------------------------------------------------------------------------
__global__ void pairs_k(const __half* __restrict__ G,
                        const int* __restrict__ ep,
                        const int* __restrict__ en,
                        float* __restrict__ out) {
    int gtid = blockIdx.x * blockDim.x + threadIdx.x;
    int lane = gtid & 31;
    int warp = gtid >> 5;
    int nwarps = (gridDim.x * blockDim.x) >> 5;
    const int total = 2 * NP;
    for (int p = warp * 2; p < total; p += nwarps * 2) {
        const int* e0 = (p < NP) ? (ep + 2 * (size_t)p)
                                 : (en + 2 * (size_t)(p - NP));
        int p1 = p + 1;
        const int* e1 = (p1 < NP) ? (ep + 2 * (size_t)p1)
                                  : (en + 2 * (size_t)(p1 - NP));
        int a = __ldg(&e0[0]), b = __ldg(&e0[1]);
        int c = __ldg(&e1[0]), d = __ldg(&e1[1]);
        float4 va = h4_to_f4(((const uint2*)(G + (size_t)a * 128))[lane]);
        float4 vb = h4_to_f4(((const uint2*)(G + (size_t)b * 128))[lane]);
        float4 vc = h4_to_f4(((const uint2*)(G + (size_t)c * 128))[lane]);
        float4 vd = h4_to_f4(((const uint2*)(G + (size_t)d * 128))[lane]);
        float s0 = va.x * vb.x + va.y * vb.y + va.z * vb.z + va.w * vb.w;
        float s1 = vc.x * vd.x + vc.y * vd.y + vc.z * vd.z + vc.w * vd.w;
#pragma unroll
        for (int o = 16; o; o >>= 1) {
            s0 += __shfl_xor_sync(0xffffffffu, s0, o);
            s1 += __shfl_xor_sync(0xffffffffu, s1, o);
        }
        if (lane == 0) { out[p] = s0; out[p1] = s1; }
    }
}

// ---------------------------------------------------------------------------
// Launch
// ---------------------------------------------------------------------------
extern "C" void kernel_launch(void* const* d_in, const int* in_sizes, int n_in,
                              void* d_out, int out_size) {
    const float* x  = (const float*)d_in[0];
    const float* W1 = (const float*)d_in[1];
    const float* b1 = (const float*)d_in[2];
    const float* W2 = (const float*)d_in[3];
    const float* b2 = (const float*)d_in[4];
    const int* edge_index = (const int*)d_in[5];
    const int* edges      = (const int*)d_in[6];
    const int* edges_neg  = (const int*)d_in[7];
    float* out = (float*)d_out;

    const int* src = edge_index;
    const int* dst = edge_index + NE;

    float *bufA, *bufB, *dinv;
    int *deg, *rowptr, *cursor, *col, *bsum, *boff;
    __nv_bfloat16* wimg;
    cudaGetSymbolAddress((void**)&bufA,   g_bufA);
    cudaGetSymbolAddress((void**)&bufB,   g_bufB);
    cudaGetSymbolAddress((void**)&deg,    g_deg);
    cudaGetSymbolAddress((void**)&dinv,   g_dinv);
    cudaGetSymbolAddress((void**)&rowptr, g_rowptr);
    cudaGetSymbolAddress((void**)&cursor, g_cursor);
    cudaGetSymbolAddress((void**)&col,    g_col);
    cudaGetSymbolAddress((void**)&bsum,   g_bsum);
    cudaGetSymbolAddress((void**)&boff,   g_boff);
    cudaGetSymbolAddress((void**)&wimg,   g_Wimg);

    __half* hH1 = (__half*)bufA;                       // H1' fp16
    __half* hH2 = (__half*)((char*)bufA + 26624000);   // H2' fp16 (second half of bufA)
    __half* gB  = (__half*)bufB;                       // G16 fp16

    const int SMEM_MMA = 512 + 2 * WIMG_HALF * 2 + 2 * TILE_M * WSTRIDE * 2;  // 104960
    cudaFuncSetAttribute(gemm1_k, cudaFuncAttributeMaxDynamicSharedMemorySize, SMEM_MMA);
    cudaFuncSetAttribute(gemm2_fused_k, cudaFuncAttributeMaxDynamicSharedMemorySize, SMEM_MMA);

    // 1. prep: degree + W split
    init_deg_k<<<(NN + 255) / 256, 256>>>(deg);
    count_deg_k<<<4096, 256>>>(dst, deg);
    wsplit_k<<<(2 * WIMG_HALF + 255) / 256, 256>>>(W1, W2, wimg);

    // 2. CSR build (scan1 also computes dinv)
    scan1_k<<<NBLK, SCAN_B>>>(deg, bsum, dinv);
    scan2_k<<<1, 256>>>(bsum, boff);
    scan3_k<<<NBLK, SCAN_B>>>(deg, boff, rowptr, cursor);
    fill_k<<<4096, 256>>>(src, dst, cursor, col);

    const int ntiles = (NN + TILE_M - 1) / TILE_M;  // 1563

    // 3. layer 1 GEMM: H1' = fp16(dinv * (x @ W1))
    gemm1_k<<<GEMM_GRID, 256, SMEM_MMA>>>(x, wimg, hH1, dinv, NN, ntiles);

    // 4. FUSED gather1 + layer 2 GEMM: H2' = fp16(dinv * (relu(agg1+b1) @ W2))
    gemm2_fused_k<<<GEMM_GRID, 256, SMEM_MMA>>>(hH1, wimg + WIMG_LAYER, b1,
                                                rowptr, col, hH2, dinv, NN, ntiles);

    // 5. layer 2 aggregation: G16 = fp16(dinv*(sum+self) + b2)
    gather2_k<<<12500, 256>>>(hH2, rowptr, col, dinv, b2, gB);

    // 6. pair dots
    pairs_k<<<8192, 256>>>(gB, edges, edges_neg, out);
}

// round 14
// speedup vs baseline: 1.1063x; 1.1063x over previous
#include <cuda_runtime.h>
#include <cuda_bf16.h>
#include <cuda_fp16.h>
#include <cstdint>

#define NN 100000
#define NE 1600000
#define NP 500000
#define DD 128
#define SCAN_B 512
#define NBLK ((NN + SCAN_B - 1) / SCAN_B)   // 196

#define WSTRIDE 136                  // bf16 elems per padded row (272 B)
#define WIMG_HALF (128 * WSTRIDE)    // 17408 elems per hi/lo image
#define WIMG_LAYER (2 * WIMG_HALF)   // 34816 elems (hi+lo) per layer
#define TILE_M 64
#define GEMM_GRID 296                // 2 CTAs/SM x 148 SMs (persistent)
#define WSPLIT_BLKS 136              // ceil(2*WIMG_HALF / 256)

// Scratch (device globals: allocation-free rule)
__device__ float g_bufA[(size_t)NN * DD];   // H1' fp16 | H2' fp16 (two regions)
__device__ float g_bufB[(size_t)NN * DD];   // AGG1 fp32, then G16 fp16
__device__ int   g_deg[NN];
__device__ float g_dinv[NN];
__device__ int   g_rowptr[NN + 1];
__device__ int   g_cursor[NN];
__device__ int   g_col[NE];
__device__ int   g_bsum[NBLK];
__device__ __align__(16) __nv_bfloat16 g_Wimg[2 * WIMG_LAYER];  // 139 KB

// ===========================================================================
// mma.sync / ldmatrix helpers (base ISA, works on compute_103 target)
// ===========================================================================
__device__ __forceinline__ uint32_t smem_u32(const void* p) {
    uint32_t a;
    asm("{ .reg .u64 t; cvta.to.shared.u64 t, %1; cvt.u32.u64 %0, t; }"
        : "=r"(a) : "l"(p));
    return a;
}
__device__ __forceinline__ void ldm_x4(uint32_t& r0, uint32_t& r1,
                                       uint32_t& r2, uint32_t& r3, uint32_t addr) {
    asm volatile("ldmatrix.sync.aligned.m8n8.x4.shared.b16 {%0,%1,%2,%3}, [%4];"
                 : "=r"(r0), "=r"(r1), "=r"(r2), "=r"(r3) : "r"(addr));
}
__device__ __forceinline__ void ldm_x2t(uint32_t& r0, uint32_t& r1, uint32_t addr) {
    asm volatile("ldmatrix.sync.aligned.m8n8.x2.trans.shared.b16 {%0,%1}, [%2];"
                 : "=r"(r0), "=r"(r1) : "r"(addr));
}
__device__ __forceinline__ void mma_bf16(float* c, uint32_t a0, uint32_t a1,
                                         uint32_t a2, uint32_t a3,
                                         uint32_t b0, uint32_t b1) {
    asm volatile(
        "mma.sync.aligned.m16n8k16.row.col.f32.bf16.bf16.f32 "
        "{%0,%1,%2,%3}, {%4,%5,%6,%7}, {%8,%9}, {%0,%1,%2,%3};"
        : "+f"(c[0]), "+f"(c[1]), "+f"(c[2]), "+f"(c[3])
        : "r"(a0), "r"(a1), "r"(a2), "r"(a3), "r"(b0), "r"(b1));
}
__device__ __forceinline__ float4 h4_to_f4(uint2 u) {
    __half2 h0 = *(__half2*)&u.x;
    __half2 h1 = *(__half2*)&u.y;
    float2 f0 = __half22float2(h0);
    float2 f1 = __half22float2(h1);
    return make_float4(f0.x, f0.y, f1.x, f1.y);
}
#define ACC4(a, v) { a.x += v.x; a.y += v.y; a.z += v.z; a.w += v.w; }

// ---------------------------------------------------------------------------
// prep: blocks [0,WSPLIT_BLKS) split W -> bf16 hi/lo images;
//       blocks [WSPLIT_BLKS, ...) count in-degrees (deg holds edge count only)
// ---------------------------------------------------------------------------
__global__ void prep_k(const float* __restrict__ W1, const float* __restrict__ W2,
                       __nv_bfloat16* __restrict__ img,
                       const int* __restrict__ dst, int* __restrict__ deg) {
    int b = blockIdx.x;
    if (b < WSPLIT_BLKS) {
        int i = b * 256 + threadIdx.x;
        if (i < 2 * WIMG_HALF) {
            int L = i / WIMG_HALF;
            int rem = i % WIMG_HALF;
            int k = rem / WSTRIDE;
            int n = rem % WSTRIDE;
            const float* W = L ? W2 : W1;
            float v = (n < 128) ? W[k * 128 + n] : 0.f;
            __nv_bfloat16 h = __float2bfloat16(v);
            __nv_bfloat16 l = __float2bfloat16(v - __bfloat162float(h));
            img[(size_t)L * WIMG_LAYER + rem] = h;
            img[(size_t)L * WIMG_LAYER + WIMG_HALF + rem] = l;
        }
    } else {
        int i = (b - WSPLIT_BLKS) * 256 + threadIdx.x;
        int stride = (gridDim.x - WSPLIT_BLKS) * 256;
        for (int e = i; e < NE; e += stride)
            atomicAdd(&deg[dst[e]], 1);
    }
}

// ---------------------------------------------------------------------------
// scan1: per-block edge-count sums + dinv = rsqrt(deg+1)
// ---------------------------------------------------------------------------
__global__ void scan1_k(const int* __restrict__ deg, int* __restrict__ bsum,
                        float* __restrict__ dinv) {
    __shared__ int s[SCAN_B];
    int t = threadIdx.x;
    int i = blockIdx.x * SCAN_B + t;
    int d = (i < NN) ? deg[i] : 0;
    if (i < NN) dinv[i] = rsqrtf((float)(d + 1));
    s[t] = d;
    __syncthreads();
    for (int off = SCAN_B / 2; off > 0; off >>= 1) {
        if (t < off) s[t] += s[t + off];
        __syncthreads();
    }
    if (t == 0) bsum[blockIdx.x] = s[0];
}

// ---------------------------------------------------------------------------
// scan23: inline block-offset scan (196 sums) + intra-block exclusive scan
// ---------------------------------------------------------------------------
__global__ void scan23_k(const int* __restrict__ deg, const int* __restrict__ bsum,
                         int* __restrict__ rowptr, int* __restrict__ cursor) {
    __shared__ int sb[NBLK];
    __shared__ int s[2][SCAN_B];
    int t = threadIdx.x;
    for (int i = t; i < NBLK; i += SCAN_B) sb[i] = bsum[i];
    __syncthreads();
    if (t == 0) {
        int run = 0;
        for (int b = 0; b < NBLK; b++) { int v = sb[b]; sb[b] = run; run += v; }
    }
    __syncthreads();
    int i = blockIdx.x * SCAN_B + t;
    int v = (i < NN) ? deg[i] : 0;
    s[0][t] = v;
    __syncthreads();
    int pp = 0;
    for (int off = 1; off < SCAN_B; off <<= 1) {
        int nv = s[pp][t] + ((t >= off) ? s[pp][t - off] : 0);
        s[1 - pp][t] = nv;
        pp = 1 - pp;
        __syncthreads();
    }
    if (i < NN) {
        int excl = s[pp][t] - v + sb[blockIdx.x];
        rowptr[i] = excl;
        cursor[i] = excl;
        if (i == NN - 1) rowptr[NN] = excl + v;
    }
}

__global__ void fill_k(const int* __restrict__ src, const int* __restrict__ dst,
                       int* __restrict__ cursor, int* __restrict__ col) {
    int i = blockIdx.x * blockDim.x + threadIdx.x;
    int stride = gridDim.x * blockDim.x;
    for (int e = i; e < NE; e += stride) {
        int d = dst[e];
        int pos = atomicAdd(&cursor[d], 1);
        col[pos] = src[e];
    }
}

// ---------------------------------------------------------------------------
// Convert TILE_M fp32 rows -> bf16 hi AND lo images in one pass.
// ---------------------------------------------------------------------------
template <bool TRANS>
__device__ __forceinline__ void convert_tile64(const float* __restrict__ X,
                                               const float* __restrict__ sbias,
                                               __nv_bfloat16* __restrict__ sAhi,
                                               __nv_bfloat16* __restrict__ sAlo,
                                               int r0, int nrows) {
    int tid = threadIdx.x;
    int m = tid >> 2;
    int c0 = (tid & 3) << 5;
    long r = (long)r0 + m;
    bool valid = r < nrows;
    const float4* Xv = (const float4*)(X + (size_t)r * 128 + c0);
    const float4* Bv = (const float4*)(sbias + c0);
    uint4* dh = (uint4*)(sAhi + m * WSTRIDE + c0);
    uint4* dl = (uint4*)(sAlo + m * WSTRIDE + c0);
#pragma unroll
    for (int j = 0; j < 4; j++) {
        float4 v0 = make_float4(0.f, 0.f, 0.f, 0.f), v1 = v0;
        if (valid) { v0 = Xv[2 * j]; v1 = Xv[2 * j + 1]; }
        if (TRANS) {
            float4 b0 = Bv[2 * j], b1 = Bv[2 * j + 1];
            v0.x = fmaxf(v0.x + b0.x, 0.f); v0.y = fmaxf(v0.y + b0.y, 0.f);
            v0.z = fmaxf(v0.z + b0.z, 0.f); v0.w = fmaxf(v0.w + b0.w, 0.f);
            v1.x = fmaxf(v1.x + b1.x, 0.f); v1.y = fmaxf(v1.y + b1.y, 0.f);
            v1.z = fmaxf(v1.z + b1.z, 0.f); v1.w = fmaxf(v1.w + b1.w, 0.f);
        }
        float f[8] = {v0.x, v0.y, v0.z, v0.w, v1.x, v1.y, v1.z, v1.w};
        uint32_t ph[4], pl[4];
#pragma unroll
        for (int q = 0; q < 4; q++) {
            float a = f[2 * q], b = f[2 * q + 1];
            __nv_bfloat16 ha = __float2bfloat16(a);
            __nv_bfloat16 hb = __float2bfloat16(b);
            __nv_bfloat16 la = __float2bfloat16(a - __bfloat162float(ha));
            __nv_bfloat16 lb = __float2bfloat16(b - __bfloat162float(hb));
            __nv_bfloat162 th; th.x = ha; th.y = hb;
            __nv_bfloat162 tl; tl.x = la; tl.y = lb;
            ph[q] = *(uint32_t*)&th;
            pl[q] = *(uint32_t*)&tl;
        }
        dh[j] = make_uint4(ph[0], ph[1], ph[2], ph[3]);
        dl[j] = make_uint4(pl[0], pl[1], pl[2], pl[3]);
    }
}

// ---------------------------------------------------------------------------
// Persistent HMMA GEMM: Hs16[N,128] = fp16( dinv * (f(X) @ W) ), 2-way bf16
// split input. W loaded to smem ONCE per block; loops over 64-row tiles.
// ---------------------------------------------------------------------------
template <bool TRANS>
__global__ void __launch_bounds__(256) gemm_mma_k(const float* __restrict__ X,
                                                  const __nv_bfloat16* __restrict__ Wimg,
                                                  const float* __restrict__ bias_in,
                                                  __half* __restrict__ Hs,
                                                  const float* __restrict__ dinv,
                                                  int nrows, int ntiles) {
    extern __shared__ __align__(16) unsigned char sm[];
    float* sbias = (float*)sm;                                    // 512 B
    __nv_bfloat16* sW   = (__nv_bfloat16*)(sm + 512);             // hi then lo
    __nv_bfloat16* sAhi = (__nv_bfloat16*)(sm + 512 + 2 * WIMG_HALF * 2);
    __nv_bfloat16* sAlo = sAhi + TILE_M * WSTRIDE;
    int tid = threadIdx.x, wid = tid >> 5, lane = tid & 31;
    int mw = wid & 3, nh = wid >> 2;

    if (TRANS && tid < 32)
        ((float4*)sbias)[tid] = ((const float4*)bias_in)[tid];
    for (int i = tid; i < (2 * WIMG_HALF * 2) / 16; i += 256)
        ((uint4*)sW)[i] = ((const uint4*)Wimg)[i];
    __syncthreads();

    uint32_t aHiBase = smem_u32(sAhi) + (mw * 16 + (lane & 15)) * (WSTRIDE * 2)
                     + (lane >> 4) * 16;
    uint32_t aLoBase = aHiBase + TILE_M * WSTRIDE * 2;
    uint32_t bBase = smem_u32(sW) + (lane & 15) * (WSTRIDE * 2) + nh * 128;

    for (int t = blockIdx.x; t < ntiles; t += gridDim.x) {
        int r0 = t * TILE_M;
        convert_tile64<TRANS>(X, sbias, sAhi, sAlo, r0, nrows);
        __syncthreads();

        float acc[8][4];
#pragma unroll
        for (int nt = 0; nt < 8; nt++)
#pragma unroll
            for (int q = 0; q < 4; q++) acc[nt][q] = 0.f;

#pragma unroll 1
        for (int ks = 0; ks < 8; ks++) {
            uint32_t a0, a1, a2, a3;
            ldm_x4(a0, a1, a2, a3, aHiBase + ks * 32);
            uint32_t bk = bBase + ks * 16 * (WSTRIDE * 2);
#pragma unroll
            for (int nt = 0; nt < 8; nt++) {
                uint32_t b0, b1, c0, c1;
                ldm_x2t(b0, b1, bk + nt * 16);
                mma_bf16(acc[nt], a0, a1, a2, a3, b0, b1);
                ldm_x2t(c0, c1, bk + nt * 16 + WIMG_HALF * 2);
                mma_bf16(acc[nt], a0, a1, a2, a3, c0, c1);
            }
        }
#pragma unroll 1
        for (int ks = 0; ks < 8; ks++) {
            uint32_t a0, a1, a2, a3;
            ldm_x4(a0, a1, a2, a3, aLoBase + ks * 32);
            uint32_t bk = bBase + ks * 16 * (WSTRIDE * 2);
#pragma unroll
            for (int nt = 0; nt < 8; nt++) {
                uint32_t b0, b1;
                ldm_x2t(b0, b1, bk + nt * 16);
                mma_bf16(acc[nt], a0, a1, a2, a3, b0, b1);
            }
        }

        int row0 = r0 + mw * 16 + (lane >> 2);
        int colb = nh * 64 + (lane & 3) * 2;
#pragma unroll
        for (int half = 0; half < 2; half++) {
            int row = row0 + half * 8;
            if (row < nrows) {
                float dv = dinv[row];
                __half* po = Hs + (size_t)row * 128 + colb;
#pragma unroll
                for (int nt = 0; nt < 8; nt++)
                    *(__half2*)(po + nt * 8) =
                        __floats2half2_rn(acc[nt][2 * half] * dv,
                                          acc[nt][2 * half + 1] * dv);
            }
        }
        __syncthreads();
    }
}

// ---------------------------------------------------------------------------
// CSR gather: sum = H'[n] + sum_in H'[s]   (fp16 reads, fp32 accum, MLP 8)
// OUT_HALF=false: AGG fp32 = dinv[n]*sum         (feeds gemm2)
// OUT_HALF=true:  G16 fp16 = dinv[n]*sum + b2    (feeds pairs)
// ---------------------------------------------------------------------------
template <bool OUT_HALF>
__global__ void gather_k(const __half* __restrict__ Hs,
                         const int* __restrict__ rowptr,
                         const int* __restrict__ col,
                         const float* __restrict__ dinv,
                         const float* __restrict__ b2,
                         void* __restrict__ OUTP) {
    int gtid = blockIdx.x * blockDim.x + threadIdx.x;
    int lane = gtid & 31;
    int w = gtid >> 5;
    int nw = (gridDim.x * blockDim.x) >> 5;
    float4 bv = make_float4(0.f, 0.f, 0.f, 0.f);
    if (OUT_HALF) bv = ((const float4*)b2)[lane];
    for (int n = w; n < NN; n += nw) {
        float4 a0 = h4_to_f4(((const uint2*)(Hs + (size_t)n * 128))[lane]);
        float4 a1 = make_float4(0.f, 0.f, 0.f, 0.f), a2 = a1, a3 = a1;
        int j = rowptr[n];
        int end = rowptr[n + 1];
        for (; j + 7 < end; j += 8) {
            int s0 = __ldg(&col[j]);
            int s1 = __ldg(&col[j + 1]);
            int s2 = __ldg(&col[j + 2]);
            int s3 = __ldg(&col[j + 3]);
            int s4 = __ldg(&col[j + 4]);
            int s5 = __ldg(&col[j + 5]);
            int s6 = __ldg(&col[j + 6]);
            int s7 = __ldg(&col[j + 7]);
            uint2 u0 = ((const uint2*)(Hs + (size_t)s0 * 128))[lane];
            uint2 u1 = ((const uint2*)(Hs + (size_t)s1 * 128))[lane];
            uint2 u2 = ((const uint2*)(Hs + (size_t)s2 * 128))[lane];
            uint2 u3 = ((const uint2*)(Hs + (size_t)s3 * 128))[lane];
            uint2 u4 = ((const uint2*)(Hs + (size_t)s4 * 128))[lane];
            uint2 u5 = ((const uint2*)(Hs + (size_t)s5 * 128))[lane];
            uint2 u6 = ((const uint2*)(Hs + (size_t)s6 * 128))[lane];
            uint2 u7 = ((const uint2*)(Hs + (size_t)s7 * 128))[lane];
            float4 v0 = h4_to_f4(u0); ACC4(a0, v0);
            float4 v1 = h4_to_f4(u1); ACC4(a1, v1);
            float4 v2 = h4_to_f4(u2); ACC4(a2, v2);
            float4 v3 = h4_to_f4(u3); ACC4(a3, v3);
            float4 v4 = h4_to_f4(u4); ACC4(a0, v4);
            float4 v5 = h4_to_f4(u5); ACC4(a1, v5);
            float4 v6 = h4_to_f4(u6); ACC4(a2, v6);
            float4 v7 = h4_to_f4(u7); ACC4(a3, v7);
        }
        for (; j + 3 < end; j += 4) {
            int s0 = __ldg(&col[j]);
            int s1 = __ldg(&col[j + 1]);
            int s2 = __ldg(&col[j + 2]);
            int s3 = __ldg(&col[j + 3]);
            float4 v0 = h4_to_f4(((const uint2*)(Hs + (size_t)s0 * 128))[lane]);
            float4 v1 = h4_to_f4(((const uint2*)(Hs + (size_t)s1 * 128))[lane]);
            float4 v2 = h4_to_f4(((const uint2*)(Hs + (size_t)s2 * 128))[lane]);
            float4 v3 = h4_to_f4(((const uint2*)(Hs + (size_t)s3 * 128))[lane]);
            ACC4(a0, v0); ACC4(a1, v1); ACC4(a2, v2); ACC4(a3, v3);
        }
        for (; j < end; j++) {
            int s0 = __ldg(&col[j]);
            float4 v0 = h4_to_f4(((const uint2*)(Hs + (size_t)s0 * 128))[lane]);
            ACC4(a0, v0);
        }
        float dn = dinv[n];
        a0.x = (a0.x + a1.x + a2.x + a3.x) * dn;
        a0.y = (a0.y + a1.y + a2.y + a3.y) * dn;
        a0.z = (a0.z + a1.z + a2.z + a3.z) * dn;
        a0.w = (a0.w + a1.w + a2.w + a3.w) * dn;
        if (OUT_HALF) {
            a0.x += bv.x; a0.y += bv.y; a0.z += bv.z; a0.w += bv.w;
            uint2 u;
            *(__half2*)&u.x = __floats2half2_rn(a0.x, a0.y);
            *(__half2*)&u.y = __floats2half2_rn(a0.z, a0.w);
            ((uint2*)((__half*)OUTP + (size_t)n * 128))[lane] = u;
        } else {
            ((float4*)((float*)OUTP + (size_t)n * 128))[lane] = a0;
        }
    }
}

// ---------------------------------------------------------------------------
// Pair dot products on fp16 G (bias pre-added): 4 pairs per warp iteration,
// int4 index loads (2 per group), 8 row loads in flight, float4 store.
// NP % 4 == 0 so a 4-group never straddles the pos/neg boundary.
// ---------------------------------------------------------------------------
__global__ void pairs_k(const __half* __restrict__ G,
                        const int* __restrict__ ep,
                        const int* __restrict__ en,
                        float* __restrict__ out) {
    int gtid = blockIdx.x * blockDim.x + threadIdx.x;
    int lane = gtid & 31;
    int warp = gtid >> 5;
    int nwarps = (gridDim.x * blockDim.x) >> 5;
    const int total = 2 * NP;
    for (int p = warp * 4; p < total; p += nwarps * 4) {
        const int* base = (p < NP) ? (ep + 2 * (size_t)p)
                                   : (en + 2 * (size_t)(p - NP));
        int4 i01 = __ldg((const int4*)base);
        int4 i23 = __ldg((const int4*)base + 1);
        uint2 ua0 = ((const uint2*)(G + (size_t)i01.x * 128))[lane];
        uint2 ub0 = ((const uint2*)(G + (size_t)i01.y * 128))[lane];
        uint2 ua1 = ((const uint2*)(G + (size_t)i01.z * 128))[lane];
        uint2 ub1 = ((const uint2*)(G + (size_t)i01.w * 128))[lane];
        uint2 ua2 = ((const uint2*)(G + (size_t)i23.x * 128))[lane];
        uint2 ub2 = ((const uint2*)(G + (size_t)i23.y * 128))[lane];
        uint2 ua3 = ((const uint2*)(G + (size_t)i23.z * 128))[lane];
        uint2 ub3 = ((const uint2*)(G + (size_t)i23.w * 128))[lane];
        float4 va0 = h4_to_f4(ua0), vb0 = h4_to_f4(ub0);
        float4 va1 = h4_to_f4(ua1), vb1 = h4_to_f4(ub1);
        float4 va2 = h4_to_f4(ua2), vb2 = h4_to_f4(ub2);
        float4 va3 = h4_to_f4(ua3), vb3 = h4_to_f4(ub3);
        float s0 = va0.x * vb0.x + va0.y * vb0.y + va0.z * vb0.z + va0.w * vb0.w;
        float s1 = va1.x * vb1.x + va1.y * vb1.y + va1.z * vb1.z + va1.w * vb1.w;
        float s2 = va2.x * vb2.x + va2.y * vb2.y + va2.z * vb2.z + va2.w * vb2.w;
        float s3 = va3.x * vb3.x + va3.y * vb3.y + va3.z * vb3.z + va3.w * vb3.w;
#pragma unroll
        for (int o = 16; o; o >>= 1) {
            s0 += __shfl_xor_sync(0xffffffffu, s0, o);
            s1 += __shfl_xor_sync(0xffffffffu, s1, o);
            s2 += __shfl_xor_sync(0xffffffffu, s2, o);
            s3 += __shfl_xor_sync(0xffffffffu, s3, o);
        }
        if (lane == 0)
            *(float4*)(out + p) = make_float4(s0, s1, s2, s3);
    }
}

// ---------------------------------------------------------------------------
// Launch
// ---------------------------------------------------------------------------
extern "C" void kernel_launch(void* const* d_in, const int* in_sizes, int n_in,
                              void* d_out, int out_size) {
    const float* x  = (const float*)d_in[0];
    const float* W1 = (const float*)d_in[1];
    const float* b1 = (const float*)d_in[2];
    const float* W2 = (const float*)d_in[3];
    const float* b2 = (const float*)d_in[4];
    const int* edge_index = (const int*)d_in[5];
    const int* edges      = (const int*)d_in[6];
    const int* edges_neg  = (const int*)d_in[7];
    float* out = (float*)d_out;

    const int* src = edge_index;
    const int* dst = edge_index + NE;

    float *bufA, *bufB, *dinv;
    int *deg, *rowptr, *cursor, *col, *bsum;
    __nv_bfloat16* wimg;
    cudaGetSymbolAddress((void**)&bufA,   g_bufA);
    cudaGetSymbolAddress((void**)&bufB,   g_bufB);
    cudaGetSymbolAddress((void**)&deg,    g_deg);
    cudaGetSymbolAddress((void**)&dinv,   g_dinv);
    cudaGetSymbolAddress((void**)&rowptr, g_rowptr);
    cudaGetSymbolAddress((void**)&cursor, g_cursor);
    cudaGetSymbolAddress((void**)&col,    g_col);
    cudaGetSymbolAddress((void**)&bsum,   g_bsum);
    cudaGetSymbolAddress((void**)&wimg,   g_Wimg);

    __half* hH1 = (__half*)bufA;                       // H1' fp16
    __half* hH2 = (__half*)((char*)bufA + 26624000);   // H2' fp16
    __half* gB  = (__half*)bufB;                       // G16 fp16

    const int SMEM_MMA = 512 + 2 * WIMG_HALF * 2 + 2 * TILE_M * WSTRIDE * 2;  // 104960
    cudaFuncSetAttribute(gemm_mma_k<false>, cudaFuncAttributeMaxDynamicSharedMemorySize, SMEM_MMA);
    cudaFuncSetAttribute(gemm_mma_k<true>,  cudaFuncAttributeMaxDynamicSharedMemorySize, SMEM_MMA);

    // 1. prep: deg=0 (memset), then fused W-split + degree count
    cudaMemsetAsync(deg, 0, NN * sizeof(int));
    prep_k<<<WSPLIT_BLKS + 4096, 256>>>(W1, W2, wimg, dst, deg);

    // 2. CSR build (scan1 computes dinv; scan23 folds block-offset scan)
    scan1_k<<<NBLK, SCAN_B>>>(deg, bsum, dinv);
    scan23_k<<<NBLK, SCAN_B>>>(deg, bsum, rowptr, cursor);
    fill_k<<<4096, 256>>>(src, dst, cursor, col);

    const int ntiles = (NN + TILE_M - 1) / TILE_M;  // 1563

    // 3. layer 1: H1' = fp16(dinv * (x @ W1));  AGG1 fp32
    gemm_mma_k<false><<<GEMM_GRID, 256, SMEM_MMA>>>(x, wimg, nullptr, hH1, dinv, NN, ntiles);
    gather_k<false><<<12500, 256>>>(hH1, rowptr, col, dinv, nullptr, bufB);

    // 4. layer 2: H2' = fp16(dinv * (relu(AGG1 + b1) @ W2));  G16 = AGG2 + b2
    gemm_mma_k<true><<<GEMM_GRID, 256, SMEM_MMA>>>(bufB, wimg + WIMG_LAYER, b1, hH2, dinv, NN, ntiles);
    gather_k<true><<<12500, 256>>>(hH2, rowptr, col, dinv, b2, gB);

    // 5. pair dots
    pairs_k<<<8192, 256>>>(gB, edges, edges_neg, out);
}

// round 15
// speedup vs baseline: 1.3545x; 1.2244x over previous
#include <cuda_runtime.h>
#include <cuda_bf16.h>
#include <cuda_fp16.h>
#include <cstdint>

#define NN 100000
#define NE 1600000
#define NP 500000
#define DD 128
#define SCAN_B 512
#define NBLK ((NN + SCAN_B - 1) / SCAN_B)   // 196

#define WSTRIDE 136                  // fp16 elems per padded row (272 B)
#define WIMG_HALF (128 * WSTRIDE)    // 17408 elems per W image (one layer)
#define TILE_M 64
#define GEMM_GRID 592                // 4 CTAs/SM x 148 SMs (persistent)
#define WSPLIT_BLKS 136              // ceil(2*WIMG_HALF / 256)
#define HALF_OFF ((size_t)NN * DD * 2)   // 25.6 MB region size

// Scratch (device globals: allocation-free rule)
__device__ float g_bufA[(size_t)NN * DD];   // [H1' fp16][H2' fp16]
__device__ float g_bufB[(size_t)NN * DD];   // [AGG1 fp16][G16 fp16]
__device__ int   g_deg[NN];
__device__ float g_dinv[NN];
__device__ int   g_rowptr[NN + 1];
__device__ int   g_cursor[NN];
__device__ int   g_col[NE];
__device__ int   g_bsum[NBLK];
__device__ __align__(16) __half g_Wimg[2 * WIMG_HALF];  // 69.6 KB (both layers)

// ===========================================================================
// mma.sync / ldmatrix helpers (base ISA, works on compute_103 target)
// ===========================================================================
__device__ __forceinline__ uint32_t smem_u32(const void* p) {
    uint32_t a;
    asm("{ .reg .u64 t; cvta.to.shared.u64 t, %1; cvt.u32.u64 %0, t; }"
        : "=r"(a) : "l"(p));
    return a;
}
__device__ __forceinline__ void ldm_x4(uint32_t& r0, uint32_t& r1,
                                       uint32_t& r2, uint32_t& r3, uint32_t addr) {
    asm volatile("ldmatrix.sync.aligned.m8n8.x4.shared.b16 {%0,%1,%2,%3}, [%4];"
                 : "=r"(r0), "=r"(r1), "=r"(r2), "=r"(r3) : "r"(addr));
}
__device__ __forceinline__ void ldm_x2t(uint32_t& r0, uint32_t& r1, uint32_t addr) {
    asm volatile("ldmatrix.sync.aligned.m8n8.x2.trans.shared.b16 {%0,%1}, [%2];"
                 : "=r"(r0), "=r"(r1) : "r"(addr));
}
__device__ __forceinline__ void mma_f16(float* c, uint32_t a0, uint32_t a1,
                                        uint32_t a2, uint32_t a3,
                                        uint32_t b0, uint32_t b1) {
    asm volatile(
        "mma.sync.aligned.m16n8k16.row.col.f32.f16.f16.f32 "
        "{%0,%1,%2,%3}, {%4,%5,%6,%7}, {%8,%9}, {%0,%1,%2,%3};"
        : "+f"(c[0]), "+f"(c[1]), "+f"(c[2]), "+f"(c[3])
        : "r"(a0), "r"(a1), "r"(a2), "r"(a3), "r"(b0), "r"(b1));
}
__device__ __forceinline__ float4 h4_to_f4(uint2 u) {
    __half2 h0 = *(__half2*)&u.x;
    __half2 h1 = *(__half2*)&u.y;
    float2 f0 = __half22float2(h0);
    float2 f1 = __half22float2(h1);
    return make_float4(f0.x, f0.y, f1.x, f1.y);
}
#define ACC4(a, v) { a.x += v.x; a.y += v.y; a.z += v.z; a.w += v.w; }

// ---------------------------------------------------------------------------
// prep: blocks [0,WSPLIT_BLKS) cast W -> fp16 k-major images;
//       blocks [WSPLIT_BLKS, ...) count in-degrees (deg = edge count only)
// ---------------------------------------------------------------------------
__global__ void prep_k(const float* __restrict__ W1, const float* __restrict__ W2,
                       __half* __restrict__ img,
                       const int* __restrict__ dst, int* __restrict__ deg) {
    int b = blockIdx.x;
    if (b < WSPLIT_BLKS) {
        int i = b * 256 + threadIdx.x;
        if (i < 2 * WIMG_HALF) {
            int L = i / WIMG_HALF;
            int rem = i % WIMG_HALF;
            int k = rem / WSTRIDE;
            int n = rem % WSTRIDE;
            const float* W = L ? W2 : W1;
            float v = (n < 128) ? W[k * 128 + n] : 0.f;
            img[i] = __float2half(v);
        }
    } else {
        int i = (b - WSPLIT_BLKS) * 256 + threadIdx.x;
        int stride = (gridDim.x - WSPLIT_BLKS) * 256;
        for (int e = i; e < NE; e += stride)
            atomicAdd(&deg[dst[e]], 1);
    }
}

// ---------------------------------------------------------------------------
// scan1: per-block edge-count sums + dinv = rsqrt(deg+1)
// ---------------------------------------------------------------------------
__global__ void scan1_k(const int* __restrict__ deg, int* __restrict__ bsum,
                        float* __restrict__ dinv) {
    __shared__ int s[SCAN_B];
    int t = threadIdx.x;
    int i = blockIdx.x * SCAN_B + t;
    int d = (i < NN) ? deg[i] : 0;
    if (i < NN) dinv[i] = rsqrtf((float)(d + 1));
    s[t] = d;
    __syncthreads();
    for (int off = SCAN_B / 2; off > 0; off >>= 1) {
        if (t < off) s[t] += s[t + off];
        __syncthreads();
    }
    if (t == 0) bsum[blockIdx.x] = s[0];
}

// ---------------------------------------------------------------------------
// scan23: inline block-offset scan + intra-block exclusive scan
// ---------------------------------------------------------------------------
__global__ void scan23_k(const int* __restrict__ deg, const int* __restrict__ bsum,
                         int* __restrict__ rowptr, int* __restrict__ cursor) {
    __shared__ int sb[NBLK];
    __shared__ int s[2][SCAN_B];
    int t = threadIdx.x;
    for (int i = t; i < NBLK; i += SCAN_B) sb[i] = bsum[i];
    __syncthreads();
    if (t == 0) {
        int run = 0;
        for (int b = 0; b < NBLK; b++) { int v = sb[b]; sb[b] = run; run += v; }
    }
    __syncthreads();
    int i = blockIdx.x * SCAN_B + t;
    int v = (i < NN) ? deg[i] : 0;
    s[0][t] = v;
    __syncthreads();
    int pp = 0;
    for (int off = 1; off < SCAN_B; off <<= 1) {
        int nv = s[pp][t] + ((t >= off) ? s[pp][t - off] : 0);
        s[1 - pp][t] = nv;
        pp = 1 - pp;
        __syncthreads();
    }
    if (i < NN) {
        int excl = s[pp][t] - v + sb[blockIdx.x];
        rowptr[i] = excl;
        cursor[i] = excl;
        if (i == NN - 1) rowptr[NN] = excl + v;
    }
}

__global__ void fill_k(const int* __restrict__ src, const int* __restrict__ dst,
                       int* __restrict__ cursor, int* __restrict__ col) {
    int i = blockIdx.x * blockDim.x + threadIdx.x;
    int stride = gridDim.x * blockDim.x;
    for (int e = i; e < NE; e += stride) {
        int d = dst[e];
        int pos = atomicAdd(&cursor[d], 1);
        col[pos] = src[e];
    }
}

// ---------------------------------------------------------------------------
// Persistent single-pass fp16 HMMA GEMM:
//   Hs16[N,128] = fp16( dinv * (f(X) @ W) )
// TRANS=false: X fp32, f = identity.
// TRANS=true:  X fp16 (AGG1), f = relu(x + bias).
// smem: bias 512 + W 34816 + A 17408 = 52736 B -> 4 CTAs/SM.
// ---------------------------------------------------------------------------
template <bool TRANS>
__global__ void __launch_bounds__(256) gemm_f16_k(const void* __restrict__ Xin,
                                                  const __half* __restrict__ Wimg,
                                                  const float* __restrict__ bias_in,
                                                  __half* __restrict__ Hs,
                                                  const float* __restrict__ dinv,
                                                  int nrows, int ntiles) {
    extern __shared__ __align__(16) unsigned char sm[];
    float* sbias = (float*)sm;                         // 512 B
    __half* sW = (__half*)(sm + 512);                  // 34816 B
    __half* sA = (__half*)(sm + 512 + WIMG_HALF * 2);  // 17408 B
    int tid = threadIdx.x, wid = tid >> 5, lane = tid & 31;
    int mw = wid & 3, nh = wid >> 2;

    if (TRANS && tid < 32)
        ((float4*)sbias)[tid] = ((const float4*)bias_in)[tid];
    for (int i = tid; i < (WIMG_HALF * 2) / 16; i += 256)
        ((uint4*)sW)[i] = ((const uint4*)Wimg)[i];
    __syncthreads();

    uint32_t aBase = smem_u32(sA) + (mw * 16 + (lane & 15)) * (WSTRIDE * 2)
                   + (lane >> 4) * 16;
    uint32_t bBase = smem_u32(sW) + (lane & 15) * (WSTRIDE * 2) + nh * 128;

    int m = tid >> 2;               // convert row within tile
    int c0 = (tid & 3) << 5;        // 32-col quarter

    for (int t = blockIdx.x; t < ntiles; t += gridDim.x) {
        int r0 = t * TILE_M;
        long r = (long)r0 + m;
        bool valid = r < nrows;
        if (!TRANS) {
            const float4* Xv = (const float4*)((const float*)Xin + (size_t)r * 128 + c0);
            uint2* dh = (uint2*)(sA + m * WSTRIDE + c0);
#pragma unroll
            for (int j = 0; j < 8; j++) {
                float4 v = valid ? Xv[j] : make_float4(0.f, 0.f, 0.f, 0.f);
                uint2 u;
                *(__half2*)&u.x = __floats2half2_rn(v.x, v.y);
                *(__half2*)&u.y = __floats2half2_rn(v.z, v.w);
                dh[j] = u;
            }
        } else {
            const uint4* Xv = (const uint4*)((const __half*)Xin + (size_t)r * 128 + c0);
            const float4* Bv = (const float4*)(sbias + c0);
            uint4* dh = (uint4*)(sA + m * WSTRIDE + c0);
#pragma unroll
            for (int j = 0; j < 4; j++) {   // 8 halves per iter
                uint4 u = valid ? Xv[j] : make_uint4(0, 0, 0, 0);
                float4 f0 = h4_to_f4(make_uint2(u.x, u.y));
                float4 f1 = h4_to_f4(make_uint2(u.z, u.w));
                float4 b0 = Bv[2 * j], b1 = Bv[2 * j + 1];
                f0.x = fmaxf(f0.x + b0.x, 0.f); f0.y = fmaxf(f0.y + b0.y, 0.f);
                f0.z = fmaxf(f0.z + b0.z, 0.f); f0.w = fmaxf(f0.w + b0.w, 0.f);
                f1.x = fmaxf(f1.x + b1.x, 0.f); f1.y = fmaxf(f1.y + b1.y, 0.f);
                f1.z = fmaxf(f1.z + b1.z, 0.f); f1.w = fmaxf(f1.w + b1.w, 0.f);
                uint4 o;
                *(__half2*)&o.x = __floats2half2_rn(f0.x, f0.y);
                *(__half2*)&o.y = __floats2half2_rn(f0.z, f0.w);
                *(__half2*)&o.z = __floats2half2_rn(f1.x, f1.y);
                *(__half2*)&o.w = __floats2half2_rn(f1.z, f1.w);
                dh[j] = o;
            }
        }
        __syncthreads();

        float acc[8][4];
#pragma unroll
        for (int nt = 0; nt < 8; nt++)
#pragma unroll
            for (int q = 0; q < 4; q++) acc[nt][q] = 0.f;

#pragma unroll 1
        for (int ks = 0; ks < 8; ks++) {
            uint32_t a0, a1, a2, a3;
            ldm_x4(a0, a1, a2, a3, aBase + ks * 32);
            uint32_t bk = bBase + ks * 16 * (WSTRIDE * 2);
#pragma unroll
            for (int nt = 0; nt < 8; nt++) {
                uint32_t b0, b1;
                ldm_x2t(b0, b1, bk + nt * 16);
                mma_f16(acc[nt], a0, a1, a2, a3, b0, b1);
            }
        }

        int row0 = r0 + mw * 16 + (lane >> 2);
        int colb = nh * 64 + (lane & 3) * 2;
#pragma unroll
        for (int half = 0; half < 2; half++) {
            int row = row0 + half * 8;
            if (row < nrows) {
                float dv = dinv[row];
                __half* po = Hs + (size_t)row * 128 + colb;
#pragma unroll
                for (int nt = 0; nt < 8; nt++)
                    *(__half2*)(po + nt * 8) =
                        __floats2half2_rn(acc[nt][2 * half] * dv,
                                          acc[nt][2 * half + 1] * dv);
            }
        }
        __syncthreads();
    }
}

// ---------------------------------------------------------------------------
// CSR gather: sum = H'[n] + sum_in H'[s]  (fp16 reads, fp32 accum, MLP 8)
// Output fp16: dinv[n]*sum  (+ b2 if ADD_BIAS).
// ---------------------------------------------------------------------------
template <bool ADD_BIAS>
__global__ void gather_k(const __half* __restrict__ Hs,
                         const int* __restrict__ rowptr,
                         const int* __restrict__ col,
                         const float* __restrict__ dinv,
                         const float* __restrict__ b2,
                         __half* __restrict__ OUTP) {
    int gtid = blockIdx.x * blockDim.x + threadIdx.x;
    int lane = gtid & 31;
    int w = gtid >> 5;
    int nw = (gridDim.x * blockDim.x) >> 5;
    float4 bv = make_float4(0.f, 0.f, 0.f, 0.f);
    if (ADD_BIAS) bv = ((const float4*)b2)[lane];
    for (int n = w; n < NN; n += nw) {
        float4 a0 = h4_to_f4(((const uint2*)(Hs + (size_t)n * 128))[lane]);
        float4 a1 = make_float4(0.f, 0.f, 0.f, 0.f), a2 = a1, a3 = a1;
        int j = rowptr[n];
        int end = rowptr[n + 1];
        for (; j + 7 < end; j += 8) {
            int s0 = __ldg(&col[j]);
            int s1 = __ldg(&col[j + 1]);
            int s2 = __ldg(&col[j + 2]);
            int s3 = __ldg(&col[j + 3]);
            int s4 = __ldg(&col[j + 4]);
            int s5 = __ldg(&col[j + 5]);
            int s6 = __ldg(&col[j + 6]);
            int s7 = __ldg(&col[j + 7]);
            uint2 u0 = ((const uint2*)(Hs + (size_t)s0 * 128))[lane];
            uint2 u1 = ((const uint2*)(Hs + (size_t)s1 * 128))[lane];
            uint2 u2 = ((const uint2*)(Hs + (size_t)s2 * 128))[lane];
            uint2 u3 = ((const uint2*)(Hs + (size_t)s3 * 128))[lane];
            uint2 u4 = ((const uint2*)(Hs + (size_t)s4 * 128))[lane];
            uint2 u5 = ((const uint2*)(Hs + (size_t)s5 * 128))[lane];
            uint2 u6 = ((const uint2*)(Hs + (size_t)s6 * 128))[lane];
            uint2 u7 = ((const uint2*)(Hs + (size_t)s7 * 128))[lane];
            float4 v0 = h4_to_f4(u0); ACC4(a0, v0);
            float4 v1 = h4_to_f4(u1); ACC4(a1, v1);
            float4 v2 = h4_to_f4(u2); ACC4(a2, v2);
            float4 v3 = h4_to_f4(u3); ACC4(a3, v3);
            float4 v4 = h4_to_f4(u4); ACC4(a0, v4);
            float4 v5 = h4_to_f4(u5); ACC4(a1, v5);
            float4 v6 = h4_to_f4(u6); ACC4(a2, v6);
            float4 v7 = h4_to_f4(u7); ACC4(a3, v7);
        }
        for (; j + 3 < end; j += 4) {
            int s0 = __ldg(&col[j]);
            int s1 = __ldg(&col[j + 1]);
            int s2 = __ldg(&col[j + 2]);
            int s3 = __ldg(&col[j + 3]);
            float4 v0 = h4_to_f4(((const uint2*)(Hs + (size_t)s0 * 128))[lane]);
            float4 v1 = h4_to_f4(((const uint2*)(Hs + (size_t)s1 * 128))[lane]);
            float4 v2 = h4_to_f4(((const uint2*)(Hs + (size_t)s2 * 128))[lane]);
            float4 v3 = h4_to_f4(((const uint2*)(Hs + (size_t)s3 * 128))[lane]);
            ACC4(a0, v0); ACC4(a1, v1); ACC4(a2, v2); ACC4(a3, v3);
        }
        for (; j < end; j++) {
            int s0 = __ldg(&col[j]);
            float4 v0 = h4_to_f4(((const uint2*)(Hs + (size_t)s0 * 128))[lane]);
            ACC4(a0, v0);
        }
        float dn = dinv[n];
        a0.x = (a0.x + a1.x + a2.x + a3.x) * dn;
        a0.y = (a0.y + a1.y + a2.y + a3.y) * dn;
        a0.z = (a0.z + a1.z + a2.z + a3.z) * dn;
        a0.w = (a0.w + a1.w + a2.w + a3.w) * dn;
        if (ADD_BIAS) {
            a0.x += bv.x; a0.y += bv.y; a0.z += bv.z; a0.w += bv.w;
        }
        uint2 u;
        *(__half2*)&u.x = __floats2half2_rn(a0.x, a0.y);
        *(__half2*)&u.y = __floats2half2_rn(a0.z, a0.w);
        ((uint2*)(OUTP + (size_t)n * 128))[lane] = u;
    }
}

// ---------------------------------------------------------------------------
// Pair dot products on fp16 G (bias pre-added): 4 pairs per warp iteration.
// ---------------------------------------------------------------------------
__global__ void pairs_k(const __half* __restrict__ G,
                        const int* __restrict__ ep,
                        const int* __restrict__ en,
                        float* __restrict__ out) {
    int gtid = blockIdx.x * blockDim.x + threadIdx.x;
    int lane = gtid & 31;
    int warp = gtid >> 5;
    int nwarps = (gridDim.x * blockDim.x) >> 5;
    const int total = 2 * NP;
    for (int p = warp * 4; p < total; p += nwarps * 4) {
        const int* base = (p < NP) ? (ep + 2 * (size_t)p)
                                   : (en + 2 * (size_t)(p - NP));
        int4 i01 = __ldg((const int4*)base);
        int4 i23 = __ldg((const int4*)base + 1);
        uint2 ua0 = ((const uint2*)(G + (size_t)i01.x * 128))[lane];
        uint2 ub0 = ((const uint2*)(G + (size_t)i01.y * 128))[lane];
        uint2 ua1 = ((const uint2*)(G + (size_t)i01.z * 128))[lane];
        uint2 ub1 = ((const uint2*)(G + (size_t)i01.w * 128))[lane];
        uint2 ua2 = ((const uint2*)(G + (size_t)i23.x * 128))[lane];
        uint2 ub2 = ((const uint2*)(G + (size_t)i23.y * 128))[lane];
        uint2 ua3 = ((const uint2*)(G + (size_t)i23.z * 128))[lane];
        uint2 ub3 = ((const uint2*)(G + (size_t)i23.w * 128))[lane];
        float4 va0 = h4_to_f4(ua0), vb0 = h4_to_f4(ub0);
        float4 va1 = h4_to_f4(ua1), vb1 = h4_to_f4(ub1);
        float4 va2 = h4_to_f4(ua2), vb2 = h4_to_f4(ub2);
        float4 va3 = h4_to_f4(ua3), vb3 = h4_to_f4(ub3);
        float s0 = va0.x * vb0.x + va0.y * vb0.y + va0.z * vb0.z + va0.w * vb0.w;
        float s1 = va1.x * vb1.x + va1.y * vb1.y + va1.z * vb1.z + va1.w * vb1.w;
        float s2 = va2.x * vb2.x + va2.y * vb2.y + va2.z * vb2.z + va2.w * vb2.w;
        float s3 = va3.x * vb3.x + va3.y * vb3.y + va3.z * vb3.z + va3.w * vb3.w;
#pragma unroll
        for (int o = 16; o; o >>= 1) {
            s0 += __shfl_xor_sync(0xffffffffu, s0, o);
            s1 += __shfl_xor_sync(0xffffffffu, s1, o);
            s2 += __shfl_xor_sync(0xffffffffu, s2, o);
            s3 += __shfl_xor_sync(0xffffffffu, s3, o);
        }
        if (lane == 0)
            *(float4*)(out + p) = make_float4(s0, s1, s2, s3);
    }
}

// ---------------------------------------------------------------------------
// Launch
// ---------------------------------------------------------------------------
extern "C" void kernel_launch(void* const* d_in, const int* in_sizes, int n_in,
                              void* d_out, int out_size) {
    const float* x  = (const float*)d_in[0];
    const float* W1 = (const float*)d_in[1];
    const float* b1 = (const float*)d_in[2];
    const float* W2 = (const float*)d_in[3];
    const float* b2 = (const float*)d_in[4];
    const int* edge_index = (const int*)d_in[5];
    const int* edges      = (const int*)d_in[6];
    const int* edges_neg  = (const int*)d_in[7];
    float* out = (float*)d_out;

    const int* src = edge_index;
    const int* dst = edge_index + NE;

    float *bufA, *bufB, *dinv;
    int *deg, *rowptr, *cursor, *col, *bsum;
    __half* wimg;
    cudaGetSymbolAddress((void**)&bufA,   g_bufA);
    cudaGetSymbolAddress((void**)&bufB,   g_bufB);
    cudaGetSymbolAddress((void**)&deg,    g_deg);
    cudaGetSymbolAddress((void**)&dinv,   g_dinv);
    cudaGetSymbolAddress((void**)&rowptr, g_rowptr);
    cudaGetSymbolAddress((void**)&cursor, g_cursor);
    cudaGetSymbolAddress((void**)&col,    g_col);
    cudaGetSymbolAddress((void**)&bsum,   g_bsum);
    cudaGetSymbolAddress((void**)&wimg,   g_Wimg);

    __half* hH1   = (__half*)bufA;                     // H1' fp16
    __half* hH2   = (__half*)((char*)bufA + HALF_OFF); // H2' fp16
    __half* hAGG1 = (__half*)bufB;                     // AGG1 fp16
    __half* gB    = (__half*)((char*)bufB + HALF_OFF); // G16 fp16

    const int SMEM_MMA = 512 + WIMG_HALF * 2 + TILE_M * WSTRIDE * 2;  // 52736
    cudaFuncSetAttribute(gemm_f16_k<false>, cudaFuncAttributeMaxDynamicSharedMemorySize, SMEM_MMA);
    cudaFuncSetAttribute(gemm_f16_k<true>,  cudaFuncAttributeMaxDynamicSharedMemorySize, SMEM_MMA);

    // 1. prep: deg=0 (memset), then fused W-cast + degree count
    cudaMemsetAsync(deg, 0, NN * sizeof(int));
    prep_k<<<WSPLIT_BLKS + 4096, 256>>>(W1, W2, wimg, dst, deg);

    // 2. CSR build
    scan1_k<<<NBLK, SCAN_B>>>(deg, bsum, dinv);
    scan23_k<<<NBLK, SCAN_B>>>(deg, bsum, rowptr, cursor);
    fill_k<<<4096, 256>>>(src, dst, cursor, col);

    const int ntiles = (NN + TILE_M - 1) / TILE_M;  // 1563

    // 3. layer 1: H1' = fp16(dinv * (x @ W1));  AGG1 fp16
    gemm_f16_k<false><<<GEMM_GRID, 256, SMEM_MMA>>>(x, wimg, nullptr, hH1, dinv, NN, ntiles);
    gather_k<false><<<12500, 256>>>(hH1, rowptr, col, dinv, nullptr, hAGG1);

    // 4. layer 2: H2' = fp16(dinv * (relu(AGG1 + b1) @ W2));  G16 = AGG2 + b2
    gemm_f16_k<true><<<GEMM_GRID, 256, SMEM_MMA>>>(hAGG1, wimg + WIMG_HALF, b1, hH2, dinv, NN, ntiles);
    gather_k<true><<<12500, 256>>>(hH2, rowptr, col, dinv, b2, gB);

    // 5. pair dots
    pairs_k<<<8192, 256>>>(gB, edges, edges_neg, out);
}

// round 16
// speedup vs baseline: 1.3651x; 1.0078x over previous
#include <cuda_runtime.h>
#include <cuda_bf16.h>
#include <cuda_fp16.h>
#include <cstdint>

#define NN 100000
#define NE 1600000
#define NP 500000
#define DD 128
#define SCAN_B 512
#define NBLK ((NN + SCAN_B - 1) / SCAN_B)   // 196

#define WSTRIDE 136                  // fp16 elems per padded row (272 B)
#define WIMG_HALF (128 * WSTRIDE)    // 17408 elems per W image (one layer)
#define TILE_M 64
#define GEMM_GRID 592                // 4 CTAs/SM x 148 SMs (persistent)
#define WSPLIT_BLKS 136              // ceil(2*WIMG_HALF / 256)
#define HALF_OFF ((size_t)NN * DD * 2)   // 25.6 MB region size

// Scratch (device globals: allocation-free rule)
__device__ float g_bufA[(size_t)NN * DD];   // [H1' fp16][H2' fp16]
__device__ float g_bufB[(size_t)NN * DD];   // [AGG1 fp16][G16 fp16]
__device__ int   g_deg[NN];
__device__ float g_dinv[NN];
__device__ int   g_rowptr[NN + 1];
__device__ int   g_cursor[NN];
__device__ int   g_col[NE];
__device__ int   g_bsum[NBLK];
__device__ __align__(16) __half g_Wimg[2 * WIMG_HALF];  // 69.6 KB (both layers)

// ===========================================================================
// mma.sync / ldmatrix helpers (base ISA, works on compute_103 target)
// ===========================================================================
__device__ __forceinline__ uint32_t smem_u32(const void* p) {
    uint32_t a;
    asm("{ .reg .u64 t; cvta.to.shared.u64 t, %1; cvt.u32.u64 %0, t; }"
        : "=r"(a) : "l"(p));
    return a;
}
__device__ __forceinline__ void ldm_x4(uint32_t& r0, uint32_t& r1,
                                       uint32_t& r2, uint32_t& r3, uint32_t addr) {
    asm volatile("ldmatrix.sync.aligned.m8n8.x4.shared.b16 {%0,%1,%2,%3}, [%4];"
                 : "=r"(r0), "=r"(r1), "=r"(r2), "=r"(r3) : "r"(addr));
}
__device__ __forceinline__ void ldm_x2t(uint32_t& r0, uint32_t& r1, uint32_t addr) {
    asm volatile("ldmatrix.sync.aligned.m8n8.x2.trans.shared.b16 {%0,%1}, [%2];"
                 : "=r"(r0), "=r"(r1) : "r"(addr));
}
__device__ __forceinline__ void mma_f16(float* c, uint32_t a0, uint32_t a1,
                                        uint32_t a2, uint32_t a3,
                                        uint32_t b0, uint32_t b1) {
    asm volatile(
        "mma.sync.aligned.m16n8k16.row.col.f32.f16.f16.f32 "
        "{%0,%1,%2,%3}, {%4,%5,%6,%7}, {%8,%9}, {%0,%1,%2,%3};"
        : "+f"(c[0]), "+f"(c[1]), "+f"(c[2]), "+f"(c[3])
        : "r"(a0), "r"(a1), "r"(a2), "r"(a3), "r"(b0), "r"(b1));
}
__device__ __forceinline__ float4 h4_to_f4(uint2 u) {
    __half2 h0 = *(__half2*)&u.x;
    __half2 h1 = *(__half2*)&u.y;
    float2 f0 = __half22float2(h0);
    float2 f1 = __half22float2(h1);
    return make_float4(f0.x, f0.y, f1.x, f1.y);
}
#define ACC4(a, v) { a.x += v.x; a.y += v.y; a.z += v.z; a.w += v.w; }

// ---------------------------------------------------------------------------
// prep: blocks [0,WSPLIT_BLKS) cast W -> fp16 k-major images;
//       blocks [WSPLIT_BLKS, ...) count in-degrees (int4-vectorized dst loads)
// ---------------------------------------------------------------------------
__global__ void prep_k(const float* __restrict__ W1, const float* __restrict__ W2,
                       __half* __restrict__ img,
                       const int* __restrict__ dst, int* __restrict__ deg) {
    int b = blockIdx.x;
    if (b < WSPLIT_BLKS) {
        int i = b * 256 + threadIdx.x;
        if (i < 2 * WIMG_HALF) {
            int L = i / WIMG_HALF;
            int rem = i % WIMG_HALF;
            int k = rem / WSTRIDE;
            int n = rem % WSTRIDE;
            const float* W = L ? W2 : W1;
            float v = (n < 128) ? W[k * 128 + n] : 0.f;
            img[i] = __float2half(v);
        }
    } else {
        int i = (b - WSPLIT_BLKS) * 256 + threadIdx.x;
        int stride = (gridDim.x - WSPLIT_BLKS) * 256;
        for (int e = i; e < NE / 4; e += stride) {
            int4 d4 = __ldg((const int4*)dst + e);
            atomicAdd(&deg[d4.x], 1);
            atomicAdd(&deg[d4.y], 1);
            atomicAdd(&deg[d4.z], 1);
            atomicAdd(&deg[d4.w], 1);
        }
    }
}

// ---------------------------------------------------------------------------
// scan1: per-block edge-count sums + dinv = rsqrt(deg+1)
// ---------------------------------------------------------------------------
__global__ void scan1_k(const int* __restrict__ deg, int* __restrict__ bsum,
                        float* __restrict__ dinv) {
    __shared__ int s[SCAN_B];
    int t = threadIdx.x;
    int i = blockIdx.x * SCAN_B + t;
    int d = (i < NN) ? deg[i] : 0;
    if (i < NN) dinv[i] = rsqrtf((float)(d + 1));
    s[t] = d;
    __syncthreads();
    for (int off = SCAN_B / 2; off > 0; off >>= 1) {
        if (t < off) s[t] += s[t + off];
        __syncthreads();
    }
    if (t == 0) bsum[blockIdx.x] = s[0];
}

// ---------------------------------------------------------------------------
// scan23: inline block-offset scan + intra-block exclusive scan
// ---------------------------------------------------------------------------
__global__ void scan23_k(const int* __restrict__ deg, const int* __restrict__ bsum,
                         int* __restrict__ rowptr, int* __restrict__ cursor) {
    __shared__ int sb[NBLK];
    __shared__ int s[2][SCAN_B];
    int t = threadIdx.x;
    for (int i = t; i < NBLK; i += SCAN_B) sb[i] = bsum[i];
    __syncthreads();
    if (t == 0) {
        int run = 0;
        for (int b = 0; b < NBLK; b++) { int v = sb[b]; sb[b] = run; run += v; }
    }
    __syncthreads();
    int i = blockIdx.x * SCAN_B + t;
    int v = (i < NN) ? deg[i] : 0;
    s[0][t] = v;
    __syncthreads();
    int pp = 0;
    for (int off = 1; off < SCAN_B; off <<= 1) {
        int nv = s[pp][t] + ((t >= off) ? s[pp][t - off] : 0);
        s[1 - pp][t] = nv;
        pp = 1 - pp;
        __syncthreads();
    }
    if (i < NN) {
        int excl = s[pp][t] - v + sb[blockIdx.x];
        rowptr[i] = excl;
        cursor[i] = excl;
        if (i == NN - 1) rowptr[NN] = excl + v;
    }
}

__global__ void fill_k(const int* __restrict__ src, const int* __restrict__ dst,
                       int* __restrict__ cursor, int* __restrict__ col) {
    int i = blockIdx.x * blockDim.x + threadIdx.x;
    int stride = gridDim.x * blockDim.x;
    for (int e = i; e < NE / 4; e += stride) {
        int4 d4 = __ldg((const int4*)dst + e);
        int4 s4 = __ldg((const int4*)src + e);
        col[atomicAdd(&cursor[d4.x], 1)] = s4.x;
        col[atomicAdd(&cursor[d4.y], 1)] = s4.y;
        col[atomicAdd(&cursor[d4.z], 1)] = s4.z;
        col[atomicAdd(&cursor[d4.w], 1)] = s4.w;
    }
}

// ---------------------------------------------------------------------------
// Persistent single-pass fp16 HMMA GEMM:
//   Hs16[N,128] = fp16( dinv * (f(X) @ W) )
// TRANS=false: X fp32, f = identity. TRANS=true: X fp16 (AGG1), f=relu(x+b).
// smem: 512 + 34816 + 17408 = 52736 B -> 4 CTAs/SM.
// ---------------------------------------------------------------------------
template <bool TRANS>
__global__ void __launch_bounds__(256) gemm_f16_k(const void* __restrict__ Xin,
                                                  const __half* __restrict__ Wimg,
                                                  const float* __restrict__ bias_in,
                                                  __half* __restrict__ Hs,
                                                  const float* __restrict__ dinv,
                                                  int nrows, int ntiles) {
    extern __shared__ __align__(16) unsigned char sm[];
    float* sbias = (float*)sm;                         // 512 B
    __half* sW = (__half*)(sm + 512);                  // 34816 B
    __half* sA = (__half*)(sm + 512 + WIMG_HALF * 2);  // 17408 B
    int tid = threadIdx.x, wid = tid >> 5, lane = tid & 31;
    int mw = wid & 3, nh = wid >> 2;

    if (TRANS && tid < 32)
        ((float4*)sbias)[tid] = ((const float4*)bias_in)[tid];
    for (int i = tid; i < (WIMG_HALF * 2) / 16; i += 256)
        ((uint4*)sW)[i] = ((const uint4*)Wimg)[i];
    __syncthreads();

    uint32_t aBase = smem_u32(sA) + (mw * 16 + (lane & 15)) * (WSTRIDE * 2)
                   + (lane >> 4) * 16;
    uint32_t bBase = smem_u32(sW) + (lane & 15) * (WSTRIDE * 2) + nh * 128;

    int m = tid >> 2;               // convert row within tile
    int c0 = (tid & 3) << 5;        // 32-col quarter

    for (int t = blockIdx.x; t < ntiles; t += gridDim.x) {
        int r0 = t * TILE_M;
        long r = (long)r0 + m;
        bool valid = r < nrows;
        if (!TRANS) {
            const float4* Xv = (const float4*)((const float*)Xin + (size_t)r * 128 + c0);
            uint2* dh = (uint2*)(sA + m * WSTRIDE + c0);
#pragma unroll
            for (int j = 0; j < 8; j++) {
                float4 v = valid ? Xv[j] : make_float4(0.f, 0.f, 0.f, 0.f);
                uint2 u;
                *(__half2*)&u.x = __floats2half2_rn(v.x, v.y);
                *(__half2*)&u.y = __floats2half2_rn(v.z, v.w);
                dh[j] = u;
            }
        } else {
            const uint4* Xv = (const uint4*)((const __half*)Xin + (size_t)r * 128 + c0);
            const float4* Bv = (const float4*)(sbias + c0);
            uint4* dh = (uint4*)(sA + m * WSTRIDE + c0);
#pragma unroll
            for (int j = 0; j < 4; j++) {   // 8 halves per iter
                uint4 u = valid ? Xv[j] : make_uint4(0, 0, 0, 0);
                float4 f0 = h4_to_f4(make_uint2(u.x, u.y));
                float4 f1 = h4_to_f4(make_uint2(u.z, u.w));
                float4 b0 = Bv[2 * j], b1 = Bv[2 * j + 1];
                f0.x = fmaxf(f0.x + b0.x, 0.f); f0.y = fmaxf(f0.y + b0.y, 0.f);
                f0.z = fmaxf(f0.z + b0.z, 0.f); f0.w = fmaxf(f0.w + b0.w, 0.f);
                f1.x = fmaxf(f1.x + b1.x, 0.f); f1.y = fmaxf(f1.y + b1.y, 0.f);
                f1.z = fmaxf(f1.z + b1.z, 0.f); f1.w = fmaxf(f1.w + b1.w, 0.f);
                uint4 o;
                *(__half2*)&o.x = __floats2half2_rn(f0.x, f0.y);
                *(__half2*)&o.y = __floats2half2_rn(f0.z, f0.w);
                *(__half2*)&o.z = __floats2half2_rn(f1.x, f1.y);
                *(__half2*)&o.w = __floats2half2_rn(f1.z, f1.w);
                dh[j] = o;
            }
        }
        __syncthreads();

        float acc[8][4];
#pragma unroll
        for (int nt = 0; nt < 8; nt++)
#pragma unroll
            for (int q = 0; q < 4; q++) acc[nt][q] = 0.f;

#pragma unroll 1
        for (int ks = 0; ks < 8; ks++) {
            uint32_t a0, a1, a2, a3;
            ldm_x4(a0, a1, a2, a3, aBase + ks * 32);
            uint32_t bk = bBase + ks * 16 * (WSTRIDE * 2);
#pragma unroll
            for (int nt = 0; nt < 8; nt++) {
                uint32_t b0, b1;
                ldm_x2t(b0, b1, bk + nt * 16);
                mma_f16(acc[nt], a0, a1, a2, a3, b0, b1);
            }
        }

        int row0 = r0 + mw * 16 + (lane >> 2);
        int colb = nh * 64 + (lane & 3) * 2;
#pragma unroll
        for (int half = 0; half < 2; half++) {
            int row = row0 + half * 8;
            if (row < nrows) {
                float dv = dinv[row];
                __half* po = Hs + (size_t)row * 128 + colb;
#pragma unroll
                for (int nt = 0; nt < 8; nt++)
                    *(__half2*)(po + nt * 8) =
                        __floats2half2_rn(acc[nt][2 * half] * dv,
                                          acc[nt][2 * half + 1] * dv);
            }
        }
        __syncthreads();
    }
}

// ---------------------------------------------------------------------------
// CSR gather, 2 nodes per warp: half-warp (16 lanes) per node, lane owns 8
// cols via uint4 loads. One row-LDG serves two rows. fp32 accumulate.
// Output fp16: dinv[n]*sum (+ b2 if ADD_BIAS).
// ---------------------------------------------------------------------------
template <bool ADD_BIAS>
__global__ void gather_k(const __half* __restrict__ Hs,
                         const int* __restrict__ rowptr,
                         const int* __restrict__ col,
                         const float* __restrict__ dinv,
                         const float* __restrict__ b2,
                         __half* __restrict__ OUTP) {
    int gtid = blockIdx.x * blockDim.x + threadIdx.x;
    int lane = gtid & 31;
    int hl = lane >> 4;          // half-warp id (0/1)
    int hlane = lane & 15;       // lane within half, owns cols hlane*8..+8
    int w = gtid >> 5;
    int nw = (gridDim.x * blockDim.x) >> 5;

    float4 bv0 = make_float4(0.f, 0.f, 0.f, 0.f), bv1 = bv0;
    if (ADD_BIAS) {
        bv0 = ((const float4*)b2)[hlane * 2];
        bv1 = ((const float4*)b2)[hlane * 2 + 1];
    }

    for (int n = 2 * w + hl; n < NN; n += 2 * nw) {
        // self row (uint4 = 8 halves)
        uint4 us = ((const uint4*)(Hs + (size_t)n * 128))[hlane];
        float4 a0 = h4_to_f4(make_uint2(us.x, us.y));
        float4 a1 = h4_to_f4(make_uint2(us.z, us.w));
        float4 c0 = make_float4(0.f, 0.f, 0.f, 0.f), c1 = c0;

        int base = rowptr[n];
        int d = rowptr[n + 1] - base;
        int dother = __shfl_xor_sync(0xffffffffu, d, 16);
        int dmax = max(d, dother);

        int j = 0;
        for (; j + 3 < dmax; j += 4) {
#pragma unroll
            for (int k = 0; k < 4; k += 2) {
                bool vA = (j + k) < d;
                bool vB = (j + k + 1) < d;
                int sA = vA ? __ldg(&col[base + j + k]) : 0;
                int sB = vB ? __ldg(&col[base + j + k + 1]) : 0;
                uint4 uA = vA ? ((const uint4*)(Hs + (size_t)sA * 128))[hlane]
                              : make_uint4(0, 0, 0, 0);
                uint4 uB = vB ? ((const uint4*)(Hs + (size_t)sB * 128))[hlane]
                              : make_uint4(0, 0, 0, 0);
                float4 fA0 = h4_to_f4(make_uint2(uA.x, uA.y));
                float4 fA1 = h4_to_f4(make_uint2(uA.z, uA.w));
                float4 fB0 = h4_to_f4(make_uint2(uB.x, uB.y));
                float4 fB1 = h4_to_f4(make_uint2(uB.z, uB.w));
                ACC4(a0, fA0); ACC4(a1, fA1);
                ACC4(c0, fB0); ACC4(c1, fB1);
            }
        }
        for (; j < dmax; j++) {
            bool vA = j < d;
            int sA = vA ? __ldg(&col[base + j]) : 0;
            uint4 uA = vA ? ((const uint4*)(Hs + (size_t)sA * 128))[hlane]
                          : make_uint4(0, 0, 0, 0);
            float4 fA0 = h4_to_f4(make_uint2(uA.x, uA.y));
            float4 fA1 = h4_to_f4(make_uint2(uA.z, uA.w));
            ACC4(a0, fA0); ACC4(a1, fA1);
        }

        float dn = dinv[n];
        a0.x = (a0.x + c0.x) * dn; a0.y = (a0.y + c0.y) * dn;
        a0.z = (a0.z + c0.z) * dn; a0.w = (a0.w + c0.w) * dn;
        a1.x = (a1.x + c1.x) * dn; a1.y = (a1.y + c1.y) * dn;
        a1.z = (a1.z + c1.z) * dn; a1.w = (a1.w + c1.w) * dn;
        if (ADD_BIAS) {
            a0.x += bv0.x; a0.y += bv0.y; a0.z += bv0.z; a0.w += bv0.w;
            a1.x += bv1.x; a1.y += bv1.y; a1.z += bv1.z; a1.w += bv1.w;
        }
        uint4 o;
        *(__half2*)&o.x = __floats2half2_rn(a0.x, a0.y);
        *(__half2*)&o.y = __floats2half2_rn(a0.z, a0.w);
        *(__half2*)&o.z = __floats2half2_rn(a1.x, a1.y);
        *(__half2*)&o.w = __floats2half2_rn(a1.z, a1.w);
        ((uint4*)(OUTP + (size_t)n * 128))[hlane] = o;
    }
}

// ---------------------------------------------------------------------------
// Pair dots, 4 pairs per warp iteration with half-warp packing:
// half hl computes pairs p+hl (sum sA) and p+2+hl (sum sB); lane owns 8 cols
// via uint4; 4-level shuffle reduce within each half (8 shfl per 4 pairs).
// ---------------------------------------------------------------------------
__global__ void pairs_k(const __half* __restrict__ G,
                        const int* __restrict__ ep,
                        const int* __restrict__ en,
                        float* __restrict__ out) {
    int gtid = blockIdx.x * blockDim.x + threadIdx.x;
    int lane = gtid & 31;
    int hl = lane >> 4;
    int hlane = lane & 15;
    int warp = gtid >> 5;
    int nwarps = (gridDim.x * blockDim.x) >> 5;
    const int total = 2 * NP;
    for (int p = warp * 4; p < total; p += nwarps * 4) {
        const int* base = (p < NP) ? (ep + 2 * (size_t)p)
                                   : (en + 2 * (size_t)(p - NP));
        // pair p+hl: indices base[2hl], base[2hl+1]; pair p+2+hl: base[4+2hl..]
        int2 iA = __ldg((const int2*)base + hl);
        int2 iB = __ldg((const int2*)base + 2 + hl);
        uint4 ua = ((const uint4*)(G + (size_t)iA.x * 128))[hlane];
        uint4 ub = ((const uint4*)(G + (size_t)iA.y * 128))[hlane];
        uint4 uc = ((const uint4*)(G + (size_t)iB.x * 128))[hlane];
        uint4 ud = ((const uint4*)(G + (size_t)iB.y * 128))[hlane];
        float4 a0 = h4_to_f4(make_uint2(ua.x, ua.y));
        float4 a1 = h4_to_f4(make_uint2(ua.z, ua.w));
        float4 b0 = h4_to_f4(make_uint2(ub.x, ub.y));
        float4 b1 = h4_to_f4(make_uint2(ub.z, ub.w));
        float4 e0 = h4_to_f4(make_uint2(uc.x, uc.y));
        float4 e1 = h4_to_f4(make_uint2(uc.z, uc.w));
        float4 f0 = h4_to_f4(make_uint2(ud.x, ud.y));
        float4 f1 = h4_to_f4(make_uint2(ud.z, ud.w));
        float sA = a0.x * b0.x + a0.y * b0.y + a0.z * b0.z + a0.w * b0.w
                 + a1.x * b1.x + a1.y * b1.y + a1.z * b1.z + a1.w * b1.w;
        float sB = e0.x * f0.x + e0.y * f0.y + e0.z * f0.z + e0.w * f0.w
                 + e1.x * f1.x + e1.y * f1.y + e1.z * f1.z + e1.w * f1.w;
#pragma unroll
        for (int o = 8; o; o >>= 1) {
            sA += __shfl_xor_sync(0xffffffffu, sA, o);
            sB += __shfl_xor_sync(0xffffffffu, sB, o);
        }
        if (hlane == 0) {
            out[p + hl] = sA;
            out[p + 2 + hl] = sB;
        }
    }
}

// ---------------------------------------------------------------------------
// Launch
// ---------------------------------------------------------------------------
extern "C" void kernel_launch(void* const* d_in, const int* in_sizes, int n_in,
                              void* d_out, int out_size) {
    const float* x  = (const float*)d_in[0];
    const float* W1 = (const float*)d_in[1];
    const float* b1 = (const float*)d_in[2];
    const float* W2 = (const float*)d_in[3];
    const float* b2 = (const float*)d_in[4];
    const int* edge_index = (const int*)d_in[5];
    const int* edges      = (const int*)d_in[6];
    const int* edges_neg  = (const int*)d_in[7];
    float* out = (float*)d_out;

    const int* src = edge_index;
    const int* dst = edge_index + NE;

    float *bufA, *bufB, *dinv;
    int *deg, *rowptr, *cursor, *col, *bsum;
    __half* wimg;
    cudaGetSymbolAddress((void**)&bufA,   g_bufA);
    cudaGetSymbolAddress((void**)&bufB,   g_bufB);
    cudaGetSymbolAddress((void**)&deg,    g_deg);
    cudaGetSymbolAddress((void**)&dinv,   g_dinv);
    cudaGetSymbolAddress((void**)&rowptr, g_rowptr);
    cudaGetSymbolAddress((void**)&cursor, g_cursor);
    cudaGetSymbolAddress((void**)&col,    g_col);
    cudaGetSymbolAddress((void**)&bsum,   g_bsum);
    cudaGetSymbolAddress((void**)&wimg,   g_Wimg);

    __half* hH1   = (__half*)bufA;                     // H1' fp16
    __half* hH2   = (__half*)((char*)bufA + HALF_OFF); // H2' fp16
    __half* hAGG1 = (__half*)bufB;                     // AGG1 fp16
    __half* gB    = (__half*)((char*)bufB + HALF_OFF); // G16 fp16

    const int SMEM_MMA = 512 + WIMG_HALF * 2 + TILE_M * WSTRIDE * 2;  // 52736
    cudaFuncSetAttribute(gemm_f16_k<false>, cudaFuncAttributeMaxDynamicSharedMemorySize, SMEM_MMA);
    cudaFuncSetAttribute(gemm_f16_k<true>,  cudaFuncAttributeMaxDynamicSharedMemorySize, SMEM_MMA);

    // 1. prep: deg=0 (memset), then fused W-cast + degree count
    cudaMemsetAsync(deg, 0, NN * sizeof(int));
    prep_k<<<WSPLIT_BLKS + 2048, 256>>>(W1, W2, wimg, dst, deg);

    // 2. CSR build
    scan1_k<<<NBLK, SCAN_B>>>(deg, bsum, dinv);
    scan23_k<<<NBLK, SCAN_B>>>(deg, bsum, rowptr, cursor);
    fill_k<<<2048, 256>>>(src, dst, cursor, col);

    const int ntiles = (NN + TILE_M - 1) / TILE_M;  // 1563

    // 3. layer 1: H1' = fp16(dinv * (x @ W1));  AGG1 fp16
    gemm_f16_k<false><<<GEMM_GRID, 256, SMEM_MMA>>>(x, wimg, nullptr, hH1, dinv, NN, ntiles);
    gather_k<false><<<6250, 256>>>(hH1, rowptr, col, dinv, nullptr, hAGG1);

    // 4. layer 2: H2' = fp16(dinv * (relu(AGG1 + b1) @ W2));  G16 = AGG2 + b2
    gemm_f16_k<true><<<GEMM_GRID, 256, SMEM_MMA>>>(hAGG1, wimg + WIMG_HALF, b1, hH2, dinv, NN, ntiles);
    gather_k<true><<<6250, 256>>>(hH2, rowptr, col, dinv, b2, gB);

    // 5. pair dots
    pairs_k<<<8192, 256>>>(gB, edges, edges_neg, out);
}